// round 5
// baseline (speedup 1.0000x reference)
#include <cuda_runtime.h>
#include <cstdint>

#define HID      100
#define NREL     16
#define NBLK     5
#define CB       20
#define MAXN     100000
#define MAXE     1600064      // E + tile padding headroom
#define WSTRIDE  2004         // per-relation stride: 2000 used + 4 pad (16B-aligned)
#define ETILE    64
#define ETHREADS 320          // 10 warps: b = t/64 (0..4), e = t%64

// ---------------- scratch (device globals; no allocations allowed) ----------------
__device__ int   g_cnt[NREL * MAXN];     // per-(rel,dst) edge counts
__device__ float g_inv[NREL * MAXN];     // 1/max(cnt,1)
__device__ int   g_hist[MAXN];           // per-dst edge counts (for sort)
__device__ int   g_cursor[MAXN];         // scatter cursors (exclusive prefix)
__device__ int   g_srcs[MAXE];           // edges sorted by dst
__device__ int   g_dsts[MAXE];
__device__ int   g_rels[MAXE];
__device__ float g_scls[MAXE];           // per-edge 1/cnt scale (0 for padding)
__device__ float g_h1[MAXN * HID];       // layer-1 output

// ---------------- setup kernels ----------------
__global__ void k_zero(int N) {
    int i = blockIdx.x * blockDim.x + threadIdx.x;
    if (i < NREL * N) g_cnt[i] = 0;
    if (i < N)        g_hist[i] = 0;
}

__global__ void k_count(const int* __restrict__ eidx, const int* __restrict__ etyp,
                        int E, int N) {
    int e = blockIdx.x * blockDim.x + threadIdx.x;
    if (e >= E) return;
    int dst = eidx[E + e];
    int rel = etyp[e];
    atomicAdd(&g_cnt[rel * N + dst], 1);
    atomicAdd(&g_hist[dst], 1);
}

__global__ void k_inv(int RN) {
    int i = blockIdx.x * blockDim.x + threadIdx.x;
    if (i < RN) g_inv[i] = 1.0f / fmaxf((float)g_cnt[i], 1.0f);
}

// single-block exclusive scan of g_hist -> g_cursor (1024 threads, chunked)
__global__ void k_scan(int N) {
    __shared__ int part[1024];
    int t = threadIdx.x;
    int chunk = (N + 1023) >> 10;
    int start = t * chunk;
    int s = 0;
    for (int i = 0; i < chunk; i++) {
        int idx = start + i;
        if (idx < N) s += g_hist[idx];
    }
    part[t] = s;
    __syncthreads();
    for (int off = 1; off < 1024; off <<= 1) {
        int v = (t >= off) ? part[t - off] : 0;
        __syncthreads();
        part[t] += v;
        __syncthreads();
    }
    int excl = (t == 0) ? 0 : part[t - 1];
    for (int i = 0; i < chunk; i++) {
        int idx = start + i;
        if (idx < N) {
            int h = g_hist[idx];
            g_cursor[idx] = excl;
            excl += h;
        }
    }
}

__global__ void k_scatter(const int* __restrict__ eidx, const int* __restrict__ etyp,
                          int E, int N) {
    int e = blockIdx.x * blockDim.x + threadIdx.x;
    if (e >= E) return;
    int src = eidx[e];
    int dst = eidx[E + e];
    int rel = etyp[e];
    int p = atomicAdd(&g_cursor[dst], 1);
    g_srcs[p] = src;
    g_dsts[p] = dst;
    g_rels[p] = rel;
    g_scls[p] = g_inv[rel * N + dst];
}

__global__ void k_pad(int E, int Epad) {
    int i = E + threadIdx.x;
    if (i < Epad) {
        g_srcs[i] = 0; g_dsts[i] = 0; g_rels[i] = 0; g_scls[i] = 0.0f;
    }
}

// ---------------- dense part: out = (relu?)x @ root + bias ----------------
// 256 threads (250 active): q = t%25 -> cols 4q..4q+3, rg = t/25 (0..9) -> 8 rows each.
// 80 rows per block. Shared: x tile (stride 101, bank-safe) + root (LDS.128).
#define GROWS 80
#define GTHREADS 256
__global__ __launch_bounds__(GTHREADS)
void k_init(const float* __restrict__ x, const float* __restrict__ root,
            const float* __restrict__ bias, float* __restrict__ out,
            int N, int do_relu) {
    extern __shared__ float sm_i[];
    float* xs = sm_i;                 // 80 * 101
    float* rs = sm_i + GROWS * 101;   // 100 * 100 (16B-aligned offset)
    int t = threadIdx.x;
    int rowbase = blockIdx.x * GROWS;

    for (int i = t; i < HID * HID; i += GTHREADS) rs[i] = root[i];
    for (int i = t; i < GROWS * HID; i += GTHREADS) {
        int rr = i / HID, c = i - rr * HID;
        int row = rowbase + rr;
        float v = (row < N) ? x[row * HID + c] : 0.0f;
        if (do_relu) v = fmaxf(v, 0.0f);
        xs[rr * 101 + c] = v;
    }
    __syncthreads();
    if (t >= 250) return;

    int q = t % 25;
    int rg = t / 25;
    float4 b4 = *reinterpret_cast<const float4*>(bias + 4 * q);
    float acc[8][4];
#pragma unroll
    for (int i = 0; i < 8; i++) {
        acc[i][0] = b4.x; acc[i][1] = b4.y; acc[i][2] = b4.z; acc[i][3] = b4.w;
    }
#pragma unroll 4
    for (int k = 0; k < HID; k++) {
        float4 r4 = *reinterpret_cast<const float4*>(rs + k * HID + 4 * q);
#pragma unroll
        for (int i = 0; i < 8; i++) {
            float xv = xs[(rg * 8 + i) * 101 + k];
            acc[i][0] = fmaf(xv, r4.x, acc[i][0]);
            acc[i][1] = fmaf(xv, r4.y, acc[i][1]);
            acc[i][2] = fmaf(xv, r4.z, acc[i][2]);
            acc[i][3] = fmaf(xv, r4.w, acc[i][3]);
        }
    }
#pragma unroll
    for (int i = 0; i < 8; i++) {
        int row = rowbase + rg * 8 + i;
        if (row < N) {
            float4 o;
            o.x = acc[i][0]; o.y = acc[i][1]; o.z = acc[i][2]; o.w = acc[i][3];
            *reinterpret_cast<float4*>(out + row * HID + 4 * q) = o;
        }
    }
}

// ---------------- edge kernel: out[dst] += (x[src] @ w[rel]) * scale ----------------
// Edges pre-sorted by dst. Persistent blocks; all 16 relations' weights live in
// shared (padded stride). Thread (b, e) computes 20 outputs of block b for edge e.
// Segmented warp shuffle-reduce over sorted-dst lanes -> atomics only at heads.
__global__ __launch_bounds__(ETHREADS)
void k_edge(const float* __restrict__ x, const float* __restrict__ w,
            float* __restrict__ out, int ntiles, int do_relu) {
    extern __shared__ float sm_e[];
    float* ws     = sm_e;                          // NREL * WSTRIDE floats
    float* xs     = sm_e + NREL * WSTRIDE;         // 100 * 65 floats (transposed, padded)
    float* sscale = xs + HID * 65;                 // 64
    int*   sdst   = (int*)(sscale + ETILE);        // 64
    int*   srel   = sdst + ETILE;                  // 64

    int t = threadIdx.x;
    for (int i = t; i < NREL * NBLK * CB * CB; i += ETHREADS) {
        int r = i / (NBLK * CB * CB);
        ws[r * WSTRIDE + (i - r * (NBLK * CB * CB))] = w[i];
    }

    int b = t / 64;       // 0..4 (uniform per warp)
    int e = t % 64;
    int lane = t & 31;

    for (int tile = blockIdx.x; tile < ntiles; tile += gridDim.x) {
        int base = tile * ETILE;
        __syncthreads();   // previous iter's readers done before restaging
        // stage: coalesced gmem reads, padded-stride transposed STS (conflict-free)
        for (int i = t; i < ETILE * HID; i += ETHREADS) {
            int ee = i / HID, c = i - ee * HID;
            float v = x[g_srcs[base + ee] * HID + c];
            if (do_relu) v = fmaxf(v, 0.0f);
            xs[c * 65 + ee] = v;
        }
        if (t < ETILE) {
            sdst[t]   = g_dsts[base + t];
            srel[t]   = g_rels[base + t];
            sscale[t] = g_scls[base + t];
        }
        __syncthreads();

        const float* wb = ws + srel[e] * WSTRIDE + b * (CB * CB);
        float acc[CB];
#pragma unroll
        for (int d = 0; d < CB; d++) acc[d] = 0.0f;
#pragma unroll
        for (int c = 0; c < CB; c++) {
            float xv = xs[(b * CB + c) * 65 + e];
            const float4* w4 = reinterpret_cast<const float4*>(wb + c * CB);
#pragma unroll
            for (int d4 = 0; d4 < 5; d4++) {
                float4 wv = w4[d4];
                acc[4 * d4 + 0] = fmaf(xv, wv.x, acc[4 * d4 + 0]);
                acc[4 * d4 + 1] = fmaf(xv, wv.y, acc[4 * d4 + 1]);
                acc[4 * d4 + 2] = fmaf(xv, wv.z, acc[4 * d4 + 2]);
                acc[4 * d4 + 3] = fmaf(xv, wv.w, acc[4 * d4 + 3]);
            }
        }
        float sc = sscale[e];
        int mydst = sdst[e];
#pragma unroll
        for (int d = 0; d < CB; d++) acc[d] *= sc;

        // segmented suffix-sum over lanes with equal dst (lanes are dst-sorted)
#pragma unroll
        for (int off = 1; off < 32; off <<= 1) {
            int odst = __shfl_down_sync(0xFFFFFFFFu, mydst, off);
            bool take = (lane + off < 32) && (odst == mydst);
#pragma unroll
            for (int d = 0; d < CB; d++) {
                float v = __shfl_down_sync(0xFFFFFFFFu, acc[d], off);
                if (take) acc[d] += v;
            }
        }
        int pdst = __shfl_up_sync(0xFFFFFFFFu, mydst, 1);
        bool head = (lane == 0) || (pdst != mydst);
        if (head) {
            float* op = out + mydst * HID + b * CB;
#pragma unroll
            for (int d = 0; d < CB; d++) atomicAdd(op + d, acc[d]);
        }
    }
}

// ---------------- host launcher ----------------
extern "C" void kernel_launch(void* const* d_in, const int* in_sizes, int n_in,
                              void* d_out, int out_size) {
    const float* node_emb = (const float*)d_in[0];
    const float* w1    = (const float*)d_in[1];
    const float* root1 = (const float*)d_in[2];
    const float* bias1 = (const float*)d_in[3];
    const float* w2    = (const float*)d_in[4];
    const float* root2 = (const float*)d_in[5];
    const float* bias2 = (const float*)d_in[6];
    const int*   eidx  = (const int*)d_in[7];
    const int*   etyp  = (const int*)d_in[8];
    float* out = (float*)d_out;

    int N = in_sizes[0] / HID;
    int E = in_sizes[8];
    if (N > MAXN) N = MAXN;
    int ntiles = (E + ETILE - 1) / ETILE;
    int Epad = ntiles * ETILE;
    if (Epad > MAXE) { Epad = MAXE; ntiles = Epad / ETILE; }

    float* h1 = nullptr;
    cudaGetSymbolAddress((void**)&h1, g_h1);

    const int EDGE_SMEM = (NREL * WSTRIDE + HID * 65 + ETILE) * 4 + ETILE * 2 * 4;
    const int INIT_SMEM = (GROWS * 101 + HID * HID) * 4;
    cudaFuncSetAttribute(k_edge, cudaFuncAttributeMaxDynamicSharedMemorySize, EDGE_SMEM);
    cudaFuncSetAttribute(k_init, cudaFuncAttributeMaxDynamicSharedMemorySize, INIT_SMEM);

    int RN = NREL * N;

    // --- preprocessing (recomputed every call; graph-capturable) ---
    k_zero<<<(RN + 255) / 256, 256>>>(N);
    k_count<<<(E + 255) / 256, 256>>>(eidx, etyp, E, N);
    k_inv<<<(RN + 255) / 256, 256>>>(RN);
    k_scan<<<1, 1024>>>(N);
    k_scatter<<<(E + 255) / 256, 256>>>(eidx, etyp, E, N);
    k_pad<<<1, ETILE>>>(E, Epad);

    int init_grid = (N + GROWS - 1) / GROWS;
    const int EDGE_GRID = 148;  // persistent, 1 block/SM (smem-limited)

    // --- layer 1: h1 = block_agg(node_emb) + node_emb @ root1 + bias1 ---
    k_init<<<init_grid, GTHREADS, INIT_SMEM>>>(node_emb, root1, bias1, h1, N, 0);
    k_edge<<<EDGE_GRID, ETHREADS, EDGE_SMEM>>>(node_emb, w1, h1, ntiles, 0);

    // --- layer 2: out = block_agg(relu(h1)) + relu(h1) @ root2 + bias2 ---
    k_init<<<init_grid, GTHREADS, INIT_SMEM>>>(h1, root2, bias2, out, N, 1);
    k_edge<<<EDGE_GRID, ETHREADS, EDGE_SMEM>>>(h1, w2, out, ntiles, 1);
}

// round 6
// speedup vs baseline: 1.1387x; 1.1387x over previous
#include <cuda_runtime.h>
#include <cstdint>

#define HID      100
#define NREL     16
#define NBLK     5
#define CB       20
#define MAXN     100000
#define MAXE     1600064      // E + tile padding headroom
#define WSTRIDE  2004         // per-relation stride: 2000 used + 4 pad (16B-aligned)
#define ETILE    64
#define ETHREADS 320          // 10 warps: b = t/64 (0..4), e = t%64
#define RESSTRIDE 108         // 16B-aligned row stride; gcd(108 mod 32,32)=4 (4-way worst)

// ---------------- scratch (device globals; no allocations allowed) ----------------
__device__ int   g_cnt[NREL * MAXN];     // per-(rel,dst) edge counts
__device__ float g_inv[NREL * MAXN];     // 1/max(cnt,1)
__device__ int   g_hist[MAXN];           // per-dst edge counts (for sort)
__device__ int   g_cursor[MAXN];         // scatter cursors (exclusive prefix)
__device__ int   g_part[128];            // scan partials
__device__ int   g_srcs[MAXE];           // edges sorted by dst
__device__ int   g_dsts[MAXE];
__device__ int   g_rels[MAXE];
__device__ float g_scls[MAXE];           // per-edge 1/cnt scale (0 for padding)
__device__ float g_h1[MAXN * HID];       // layer-1 output

// ---------------- setup kernels ----------------
__global__ void k_zero(int N) {
    int i = blockIdx.x * blockDim.x + threadIdx.x;
    if (i < NREL * N) g_cnt[i] = 0;
    if (i < N)        g_hist[i] = 0;
}

__global__ void k_count(const int* __restrict__ eidx, const int* __restrict__ etyp,
                        int E, int N) {
    int e = blockIdx.x * blockDim.x + threadIdx.x;
    if (e >= E) return;
    int dst = eidx[E + e];
    int rel = etyp[e];
    atomicAdd(&g_cnt[rel * N + dst], 1);
    atomicAdd(&g_hist[dst], 1);
}

__global__ void k_inv(int RN) {
    int i = blockIdx.x * blockDim.x + threadIdx.x;
    if (i < RN) g_inv[i] = 1.0f / fmaxf((float)g_cnt[i], 1.0f);
}

// ---------- 3-phase grid scan of g_hist -> g_cursor (exclusive) ----------
__global__ void k_scan1(int N) {                 // per-block sums
    __shared__ int sh[1024];
    int t = threadIdx.x;
    int i = blockIdx.x * 1024 + t;
    sh[t] = (i < N) ? g_hist[i] : 0;
    __syncthreads();
    for (int off = 512; off > 0; off >>= 1) {
        if (t < off) sh[t] += sh[t + off];
        __syncthreads();
    }
    if (t == 0) g_part[blockIdx.x] = sh[0];
}

__global__ void k_scan2(int nb) {                // exclusive scan of partials (1 block)
    __shared__ int sh[128];
    int t = threadIdx.x;
    sh[t] = (t < nb) ? g_part[t] : 0;
    __syncthreads();
    for (int off = 1; off < 128; off <<= 1) {
        int v = (t >= off) ? sh[t - off] : 0;
        __syncthreads();
        sh[t] += v;
        __syncthreads();
    }
    if (t < nb) g_part[t] = sh[t] - ((t < nb) ? ((t == 0) ? sh[0] : sh[t] - sh[t - 1]) : 0) * 0
                            ; // placeholder (replaced below)
    // proper exclusive: value = inclusive - own input; recompute own input:
    if (t < nb) {
        int incl = sh[t];
        int own  = (t == 0) ? incl : incl - sh[t - 1];
        g_part[t] = incl - own;
    }
}

__global__ void k_scan3(int N) {                 // intra-block exclusive scan + offset
    __shared__ int sh[1024];
    int t = threadIdx.x;
    int i = blockIdx.x * 1024 + t;
    int x = (i < N) ? g_hist[i] : 0;
    sh[t] = x;
    __syncthreads();
    for (int off = 1; off < 1024; off <<= 1) {
        int v = (t >= off) ? sh[t - off] : 0;
        __syncthreads();
        sh[t] += v;
        __syncthreads();
    }
    if (i < N) g_cursor[i] = sh[t] - x + g_part[blockIdx.x];
}

__global__ void k_scatter(const int* __restrict__ eidx, const int* __restrict__ etyp,
                          int E, int N) {
    int e = blockIdx.x * blockDim.x + threadIdx.x;
    if (e >= E) return;
    int src = eidx[e];
    int dst = eidx[E + e];
    int rel = etyp[e];
    int p = atomicAdd(&g_cursor[dst], 1);
    g_srcs[p] = src;
    g_dsts[p] = dst;
    g_rels[p] = rel;
    g_scls[p] = g_inv[rel * N + dst];
}

__global__ void k_pad(int E, int Epad) {
    int i = E + threadIdx.x;
    if (i < Epad) {
        g_srcs[i] = 0; g_dsts[i] = 0; g_rels[i] = 0; g_scls[i] = 0.0f;
    }
}

// ---------------- dense part: out = (relu?)x @ root + bias ----------------
#define GROWS 80
#define GTHREADS 256
__global__ __launch_bounds__(GTHREADS)
void k_init(const float* __restrict__ x, const float* __restrict__ root,
            const float* __restrict__ bias, float* __restrict__ out,
            int N, int do_relu) {
    extern __shared__ float sm_i[];
    float* xs = sm_i;                 // 80 * 101
    float* rs = sm_i + GROWS * 101;   // 100 * 100
    int t = threadIdx.x;
    int rowbase = blockIdx.x * GROWS;

    for (int i = t; i < HID * HID; i += GTHREADS) rs[i] = root[i];
    for (int i = t; i < GROWS * HID; i += GTHREADS) {
        int rr = i / HID, c = i - rr * HID;
        int row = rowbase + rr;
        float v = (row < N) ? x[row * HID + c] : 0.0f;
        if (do_relu) v = fmaxf(v, 0.0f);
        xs[rr * 101 + c] = v;
    }
    __syncthreads();
    if (t >= 250) return;

    int q = t % 25;
    int rg = t / 25;
    float4 b4 = *reinterpret_cast<const float4*>(bias + 4 * q);
    float acc[8][4];
#pragma unroll
    for (int i = 0; i < 8; i++) {
        acc[i][0] = b4.x; acc[i][1] = b4.y; acc[i][2] = b4.z; acc[i][3] = b4.w;
    }
#pragma unroll 4
    for (int k = 0; k < HID; k++) {
        float4 r4 = *reinterpret_cast<const float4*>(rs + k * HID + 4 * q);
#pragma unroll
        for (int i = 0; i < 8; i++) {
            float xv = xs[(rg * 8 + i) * 101 + k];
            acc[i][0] = fmaf(xv, r4.x, acc[i][0]);
            acc[i][1] = fmaf(xv, r4.y, acc[i][1]);
            acc[i][2] = fmaf(xv, r4.z, acc[i][2]);
            acc[i][3] = fmaf(xv, r4.w, acc[i][3]);
        }
    }
#pragma unroll
    for (int i = 0; i < 8; i++) {
        int row = rowbase + rg * 8 + i;
        if (row < N) {
            float4 o;
            o.x = acc[i][0]; o.y = acc[i][1]; o.z = acc[i][2]; o.w = acc[i][3];
            *reinterpret_cast<float4*>(out + row * HID + 4 * q) = o;
        }
    }
}

// ---------------- edge kernel ----------------
// Edges globally sorted by dst. Per tile of 64 edges:
//  1. stage x rows (transposed, padded) + edge meta into shared
//  2. stable counting-sort the 64 slots by relation (smem permutation sinv)
//  3. compute transform in REL-GROUPED order (warps rel-uniform -> weight LDS
//     broadcasts), write scaled 20-vec to res[orig_slot]
//  4. dst-segmented warp shuffle reduce over res in original dst-sorted order,
//     atomics only at segment heads (~5 dsts/tile)
__global__ __launch_bounds__(ETHREADS)
void k_edge(const float* __restrict__ x, const float* __restrict__ w,
            float* __restrict__ out, int ntiles, int do_relu) {
    extern __shared__ float sm_e[];
    float* ws     = sm_e;                             // 16 * 2004
    float* xs     = ws + NREL * WSTRIDE;              // 100 * 65
    float* res    = xs + HID * 65;                    // 64 * 108 (16B aligned)
    float* sscale = res + ETILE * RESSTRIDE;          // 64
    int*   sdst   = (int*)(sscale + ETILE);           // 64
    int*   srel   = sdst + ETILE;                     // 64
    int*   sinv   = srel + ETILE;                     // 64
    int*   scnt   = sinv + ETILE;                     // 2 * 16
    int*   soff   = scnt + 32;                        // 16

    int t = threadIdx.x;
    for (int i = t; i < NREL * NBLK * CB * CB; i += ETHREADS) {
        int r = i / (NBLK * CB * CB);
        ws[r * WSTRIDE + (i - r * (NBLK * CB * CB))] = w[i];
    }

    int b = t / 64;       // 0..4 (uniform per warp)
    int e = t % 64;
    int lane = t & 31;
    int sw = t >> 5;      // warp id; warps 0,1 own the 64 slots for sorting

    for (int tile = blockIdx.x; tile < ntiles; tile += gridDim.x) {
        int base = tile * ETILE;
        __syncthreads();   // previous iter's readers done before restaging

        // ---- stage ----
        for (int i = t; i < ETILE * HID; i += ETHREADS) {
            int ee = i / HID, c = i - ee * HID;
            float v = x[g_srcs[base + ee] * HID + c];
            if (do_relu) v = fmaxf(v, 0.0f);
            xs[c * 65 + ee] = v;
        }
        if (t < ETILE) {
            sdst[t]   = g_dsts[base + t];
            srel[t]   = g_rels[base + t];
            sscale[t] = g_scls[base + t];
        }
        if (t < 32) scnt[t] = 0;
        __syncthreads();

        // ---- in-tile stable counting sort by relation (threads 0..63) ----
        int myrank = 0, myrel = 0;
        if (t < 64) {
            myrel = srel[t];
            unsigned m = __match_any_sync(0xFFFFFFFFu, myrel);
            myrank = __popc(m & ((1u << lane) - 1u));
            if ((__ffs(m) - 1) == lane) scnt[sw * 16 + myrel] = __popc(m);
        }
        __syncthreads();
        if (t < 16) {
            int tot = scnt[t] + scnt[16 + t];
            int run = tot;
#pragma unroll
            for (int d = 1; d < 16; d <<= 1) {
                int v = __shfl_up_sync(0xFFFFu, run, d);
                if (t >= d) run += v;
            }
            soff[t] = run - tot;   // exclusive offset per relation
        }
        __syncthreads();
        if (t < 64) {
            int pos = soff[myrel] + myrank + (sw == 1 ? scnt[myrel] : 0);
            sinv[pos] = t;
        }
        __syncthreads();

        // ---- transform in rel-grouped order; route result to original slot ----
        {
            int o   = sinv[e];
            int rel = srel[o];
            float sc = sscale[o];
            const float* wb = ws + rel * WSTRIDE + b * (CB * CB);
            float acc[CB];
#pragma unroll
            for (int d = 0; d < CB; d++) acc[d] = 0.0f;
#pragma unroll
            for (int c = 0; c < CB; c++) {
                float xv = xs[(b * CB + c) * 65 + o];
                const float4* w4 = reinterpret_cast<const float4*>(wb + c * CB);
#pragma unroll
                for (int d4 = 0; d4 < 5; d4++) {
                    float4 wv = w4[d4];
                    acc[4 * d4 + 0] = fmaf(xv, wv.x, acc[4 * d4 + 0]);
                    acc[4 * d4 + 1] = fmaf(xv, wv.y, acc[4 * d4 + 1]);
                    acc[4 * d4 + 2] = fmaf(xv, wv.z, acc[4 * d4 + 2]);
                    acc[4 * d4 + 3] = fmaf(xv, wv.w, acc[4 * d4 + 3]);
                }
            }
            float4* rp = reinterpret_cast<float4*>(res + o * RESSTRIDE + b * CB);
#pragma unroll
            for (int d4 = 0; d4 < 5; d4++) {
                float4 v;
                v.x = acc[4 * d4 + 0] * sc; v.y = acc[4 * d4 + 1] * sc;
                v.z = acc[4 * d4 + 2] * sc; v.w = acc[4 * d4 + 3] * sc;
                rp[d4] = v;
            }
        }
        __syncthreads();

        // ---- dst-segmented reduce in original (dst-sorted) order ----
        {
            float acc[CB];
            const float4* rp = reinterpret_cast<const float4*>(res + e * RESSTRIDE + b * CB);
#pragma unroll
            for (int d4 = 0; d4 < 5; d4++) {
                float4 v = rp[d4];
                acc[4 * d4 + 0] = v.x; acc[4 * d4 + 1] = v.y;
                acc[4 * d4 + 2] = v.z; acc[4 * d4 + 3] = v.w;
            }
            int mydst = sdst[e];
#pragma unroll
            for (int off = 1; off < 32; off <<= 1) {
                int odst = __shfl_down_sync(0xFFFFFFFFu, mydst, off);
                bool take = (lane + off < 32) && (odst == mydst);
#pragma unroll
                for (int d = 0; d < CB; d++) {
                    float v = __shfl_down_sync(0xFFFFFFFFu, acc[d], off);
                    if (take) acc[d] += v;
                }
            }
            int pdst = __shfl_up_sync(0xFFFFFFFFu, mydst, 1);
            bool head = (lane == 0) || (pdst != mydst);
            if (head) {
                float* op = out + mydst * HID + b * CB;
#pragma unroll
                for (int d = 0; d < CB; d++) atomicAdd(op + d, acc[d]);
            }
        }
    }
}

// ---------------- host launcher ----------------
extern "C" void kernel_launch(void* const* d_in, const int* in_sizes, int n_in,
                              void* d_out, int out_size) {
    const float* node_emb = (const float*)d_in[0];
    const float* w1    = (const float*)d_in[1];
    const float* root1 = (const float*)d_in[2];
    const float* bias1 = (const float*)d_in[3];
    const float* w2    = (const float*)d_in[4];
    const float* root2 = (const float*)d_in[5];
    const float* bias2 = (const float*)d_in[6];
    const int*   eidx  = (const int*)d_in[7];
    const int*   etyp  = (const int*)d_in[8];
    float* out = (float*)d_out;

    int N = in_sizes[0] / HID;
    int E = in_sizes[8];
    if (N > MAXN) N = MAXN;
    int ntiles = (E + ETILE - 1) / ETILE;
    int Epad = ntiles * ETILE;
    if (Epad > MAXE) { Epad = MAXE; ntiles = Epad / ETILE; }

    float* h1 = nullptr;
    cudaGetSymbolAddress((void**)&h1, g_h1);

    const int EDGE_SMEM = (NREL * WSTRIDE + HID * 65 + ETILE * RESSTRIDE + ETILE) * 4
                        + (ETILE * 3 + 32 + 16) * 4;
    const int INIT_SMEM = (GROWS * 101 + HID * HID) * 4;
    cudaFuncSetAttribute(k_edge, cudaFuncAttributeMaxDynamicSharedMemorySize, EDGE_SMEM);
    cudaFuncSetAttribute(k_init, cudaFuncAttributeMaxDynamicSharedMemorySize, INIT_SMEM);

    int RN = NREL * N;
    int nb = (N + 1023) / 1024;   // <= 98 < 128

    // --- preprocessing (recomputed every call; graph-capturable) ---
    k_zero<<<(RN + 255) / 256, 256>>>(N);
    k_count<<<(E + 255) / 256, 256>>>(eidx, etyp, E, N);
    k_inv<<<(RN + 255) / 256, 256>>>(RN);
    k_scan1<<<nb, 1024>>>(N);
    k_scan2<<<1, 128>>>(nb);
    k_scan3<<<nb, 1024>>>(N);
    k_scatter<<<(E + 255) / 256, 256>>>(eidx, etyp, E, N);
    k_pad<<<1, ETILE>>>(E, Epad);

    int init_grid = (N + GROWS - 1) / GROWS;
    const int EDGE_GRID = 148;

    // --- layer 1 ---
    k_init<<<init_grid, GTHREADS, INIT_SMEM>>>(node_emb, root1, bias1, h1, N, 0);
    k_edge<<<EDGE_GRID, ETHREADS, EDGE_SMEM>>>(node_emb, w1, h1, ntiles, 0);

    // --- layer 2 ---
    k_init<<<init_grid, GTHREADS, INIT_SMEM>>>(h1, root2, bias2, out, N, 1);
    k_edge<<<EDGE_GRID, ETHREADS, EDGE_SMEM>>>(h1, w2, out, ntiles, 1);
}

// round 7
// speedup vs baseline: 1.3855x; 1.2167x over previous
#include <cuda_runtime.h>
#include <cstdint>

#define HID      100
#define NREL     16
#define NBLK     5
#define CB       20
#define MAXN     100000
#define MAXE     1600064      // >= ntiles*ETILE for E=1.6M
#define WSTRIDE  2004         // per-relation weight stride (2000 used + 4 pad, 16B aligned)
#define ETILE    96
#define ETHREADS 480          // 15 warps: b = t/96 (0..4), e = t%96; warp-uniform b
#define XSTR     97           // xs transposed stride (97 mod 32 = 1 -> conflict-free)

// ---------------- scratch (device globals; no allocations allowed) ----------------
__device__ int   g_cnt[NREL * MAXN];     // per-(rel,dst) edge counts
__device__ int   g_hist[MAXN];           // per-dst edge counts (for sort)
__device__ int   g_cursor[MAXN];         // scatter cursors (exclusive prefix)
__device__ int   g_chain[256];           // lookback-scan chain (0 = not ready)
__device__ int   g_srcs[MAXE];           // edges sorted by dst
__device__ int   g_dsts[MAXE];
__device__ int   g_rels[MAXE];
__device__ float g_scls[MAXE];           // per-edge 1/cnt scale (0 for padding)
__device__ float g_h1[MAXN * HID];       // layer-1 output (relu'd in place)

// ---------------- cp.async helpers ----------------
__device__ __forceinline__ void cpa4(uint32_t s, const void* g) {
    asm volatile("cp.async.ca.shared.global [%0], [%1], 4;" :: "r"(s), "l"(g));
}
__device__ __forceinline__ uint32_t smaddr(const void* p) {
    return (uint32_t)__cvta_generic_to_shared(p);
}
#define CPA_COMMIT() asm volatile("cp.async.commit_group;" ::: "memory")
#define CPA_WAIT1()  asm volatile("cp.async.wait_group 1;" ::: "memory")

// ---------------- setup kernels ----------------
__global__ void k_zero(int N, int RN, int E, int Epad) {
    int i = blockIdx.x * blockDim.x + threadIdx.x;
    if (i < RN)  g_cnt[i] = 0;
    if (i < N)   g_hist[i] = 0;
    if (i < 256) g_chain[i] = 0;
    if (i < Epad - E) {                 // pad tail edges: inert (scale 0)
        g_srcs[E + i] = 0; g_dsts[E + i] = 0; g_rels[E + i] = 0; g_scls[E + i] = 0.0f;
    }
}

__global__ void k_count(const int* __restrict__ eidx, const int* __restrict__ etyp,
                        int E, int N) {
    int e = blockIdx.x * blockDim.x + threadIdx.x;
    if (e >= E) return;
    int dst = eidx[E + e];
    int rel = etyp[e];
    atomicAdd(&g_cnt[rel * N + dst], 1);
    atomicAdd(&g_hist[dst], 1);
}

// single-pass exclusive scan of g_hist -> g_cursor, decoupled chain.
// 98 blocks of 1024 (all resident on 148 SMs -> chained spin is safe).
__global__ void k_scan(int N) {
    __shared__ int sh[1024];
    __shared__ int s_prev;
    int t = threadIdx.x, blk = blockIdx.x;
    int i = blk * 1024 + t;
    int x = (i < N) ? g_hist[i] : 0;
    sh[t] = x;
    __syncthreads();
    for (int off = 1; off < 1024; off <<= 1) {
        int v = (t >= off) ? sh[t - off] : 0;
        __syncthreads();
        sh[t] += v;
        __syncthreads();
    }
    if (t == 0) {
        int prev = 0;
        if (blk > 0) {
            int v;
            do {
                v = atomicAdd(&g_chain[blk - 1], 0);
                if (v == 0) __nanosleep(60);
            } while (v == 0);
            prev = v - 1;
        }
        atomicExch(&g_chain[blk], prev + sh[1023] + 1);
        s_prev = prev;
    }
    __syncthreads();
    if (i < N) g_cursor[i] = s_prev + sh[t] - x;
}

__global__ void k_scatter(const int* __restrict__ eidx, const int* __restrict__ etyp,
                          int E, int N) {
    int e = blockIdx.x * blockDim.x + threadIdx.x;
    if (e >= E) return;
    int src = eidx[e];
    int dst = eidx[E + e];
    int rel = etyp[e];
    int p = atomicAdd(&g_cursor[dst], 1);
    g_srcs[p] = src;
    g_dsts[p] = dst;
    g_rels[p] = rel;
    int c = g_cnt[rel * N + dst];
    g_scls[p] = 1.0f / (float)(c > 1 ? c : 1);
}

__global__ void k_relu(float* __restrict__ a, int n) {
    int i = blockIdx.x * blockDim.x + threadIdx.x;
    if (i < n) a[i] = fmaxf(a[i], 0.0f);
}

// ---------------- dense part: out = x @ root + bias ----------------
#define GROWS 80
#define GTHREADS 256
__global__ __launch_bounds__(GTHREADS)
void k_init(const float* __restrict__ x, const float* __restrict__ root,
            const float* __restrict__ bias, float* __restrict__ out, int N) {
    extern __shared__ float sm_i[];
    float* xs = sm_i;                 // 80 * 101
    float* rs = sm_i + GROWS * 101;   // 100 * 100
    int t = threadIdx.x;
    int rowbase = blockIdx.x * GROWS;

    for (int i = t; i < HID * HID; i += GTHREADS) rs[i] = root[i];
    for (int i = t; i < GROWS * HID; i += GTHREADS) {
        int rr = i / HID, c = i - rr * HID;
        int row = rowbase + rr;
        xs[rr * 101 + c] = (row < N) ? x[row * HID + c] : 0.0f;
    }
    __syncthreads();
    if (t >= 250) return;

    int q = t % 25;
    int rg = t / 25;
    float4 b4 = *reinterpret_cast<const float4*>(bias + 4 * q);
    float acc[8][4];
#pragma unroll
    for (int i = 0; i < 8; i++) {
        acc[i][0] = b4.x; acc[i][1] = b4.y; acc[i][2] = b4.z; acc[i][3] = b4.w;
    }
#pragma unroll 4
    for (int k = 0; k < HID; k++) {
        float4 r4 = *reinterpret_cast<const float4*>(rs + k * HID + 4 * q);
#pragma unroll
        for (int i = 0; i < 8; i++) {
            float xv = xs[(rg * 8 + i) * 101 + k];
            acc[i][0] = fmaf(xv, r4.x, acc[i][0]);
            acc[i][1] = fmaf(xv, r4.y, acc[i][1]);
            acc[i][2] = fmaf(xv, r4.z, acc[i][2]);
            acc[i][3] = fmaf(xv, r4.w, acc[i][3]);
        }
    }
#pragma unroll
    for (int i = 0; i < 8; i++) {
        int row = rowbase + rg * 8 + i;
        if (row < N) {
            float4 o;
            o.x = acc[i][0]; o.y = acc[i][1]; o.z = acc[i][2]; o.w = acc[i][3];
            *reinterpret_cast<float4*>(out + row * HID + 4 * q) = o;
        }
    }
}

// ---------------- edge kernel ----------------
// Edges globally sorted by dst. Double-buffered cp.async pipeline:
// prefetch tile t+1 (x rows transposed into xs[c*97+e] + meta) while
// computing tile t. Thread (b,e): 20 outputs of block b for edge e.
// Dst-segmented warp shuffle reduce -> atomics only at segment heads.
__device__ __forceinline__ void stage_tile(int tile, const float* __restrict__ x,
                                           float* xs, int* md, int t) {
    int base = tile * ETILE;
#pragma unroll
    for (int k = 0; k < (ETILE * HID) / ETHREADS; k++) {   // 20 iters
        int i = t + k * ETHREADS;
        int ee = i / HID, c = i - ee * HID;
        int src = __ldg(&g_srcs[base + ee]);
        cpa4(smaddr(xs + c * XSTR + ee), x + src * HID + c);
    }
    if (t < ETILE) {
        cpa4(smaddr(md + t),             &g_dsts[base + t]);
        cpa4(smaddr(md + ETILE + t),     &g_rels[base + t]);
        cpa4(smaddr(md + 2 * ETILE + t), &g_scls[base + t]);
    }
}

__global__ __launch_bounds__(ETHREADS)
void k_edge(const float* __restrict__ x, const float* __restrict__ w,
            float* __restrict__ out, int ntiles) {
    extern __shared__ float sm_e[];
    float* ws  = sm_e;                               // 16 * 2004
    float* xs0 = ws + NREL * WSTRIDE;                // 100 * 97
    float* xs1 = xs0 + HID * XSTR;                   // 100 * 97
    int*   md0 = (int*)(xs1 + HID * XSTR);           // 3 * 96
    int*   md1 = md0 + 3 * ETILE;                    // 3 * 96

    int t = threadIdx.x;
    for (int i = t; i < NREL * NBLK * CB * CB; i += ETHREADS) {
        int r = i / (NBLK * CB * CB);
        ws[r * WSTRIDE + (i - r * (NBLK * CB * CB))] = w[i];
    }

    int b = t / ETILE;          // 0..4, warp-uniform
    int e = t - b * ETILE;      // 0..95, 32-aligned per warp
    int lane = t & 31;

    int first = blockIdx.x;
    if (first < ntiles) stage_tile(first, x, xs0, md0, t);
    CPA_COMMIT();

    int parity = 0;
    for (int tile = first; tile < ntiles; tile += gridDim.x) {
        int nxt = tile + gridDim.x;
        if (nxt < ntiles) stage_tile(nxt, x, parity ? xs0 : xs1, parity ? md0 : md1, t);
        CPA_COMMIT();
        CPA_WAIT1();            // current tile's group complete
        __syncthreads();

        const float* xs = parity ? xs1 : xs0;
        const int*   md = parity ? md1 : md0;

        int   mydst = md[e];
        int   rel   = md[ETILE + e];
        float sc    = __int_as_float(md[2 * ETILE + e]);
        const float* wb = ws + rel * WSTRIDE + b * (CB * CB);

        float acc[CB];
#pragma unroll
        for (int d = 0; d < CB; d++) acc[d] = 0.0f;
#pragma unroll
        for (int c = 0; c < CB; c++) {
            float xv = xs[(b * CB + c) * XSTR + e];
            const float4* w4 = reinterpret_cast<const float4*>(wb + c * CB);
#pragma unroll
            for (int d4 = 0; d4 < 5; d4++) {
                float4 wv = w4[d4];
                acc[4 * d4 + 0] = fmaf(xv, wv.x, acc[4 * d4 + 0]);
                acc[4 * d4 + 1] = fmaf(xv, wv.y, acc[4 * d4 + 1]);
                acc[4 * d4 + 2] = fmaf(xv, wv.z, acc[4 * d4 + 2]);
                acc[4 * d4 + 3] = fmaf(xv, wv.w, acc[4 * d4 + 3]);
            }
        }
#pragma unroll
        for (int d = 0; d < CB; d++) acc[d] *= sc;

        // segmented suffix-sum over lanes with equal dst (lanes are dst-sorted)
#pragma unroll
        for (int off = 1; off < 32; off <<= 1) {
            int odst = __shfl_down_sync(0xFFFFFFFFu, mydst, off);
            bool take = (lane + off < 32) && (odst == mydst);
#pragma unroll
            for (int d = 0; d < CB; d++) {
                float v = __shfl_down_sync(0xFFFFFFFFu, acc[d], off);
                if (take) acc[d] += v;
            }
        }
        int pdst = __shfl_up_sync(0xFFFFFFFFu, mydst, 1);
        bool head = (lane == 0) || (pdst != mydst);
        if (head) {
            float* op = out + mydst * HID + b * CB;
#pragma unroll
            for (int d = 0; d < CB; d++) atomicAdd(op + d, acc[d]);
        }
        __syncthreads();        // readers done before buffer is re-staged
        parity ^= 1;
    }
}

// ---------------- host launcher ----------------
extern "C" void kernel_launch(void* const* d_in, const int* in_sizes, int n_in,
                              void* d_out, int out_size) {
    const float* node_emb = (const float*)d_in[0];
    const float* w1    = (const float*)d_in[1];
    const float* root1 = (const float*)d_in[2];
    const float* bias1 = (const float*)d_in[3];
    const float* w2    = (const float*)d_in[4];
    const float* root2 = (const float*)d_in[5];
    const float* bias2 = (const float*)d_in[6];
    const int*   eidx  = (const int*)d_in[7];
    const int*   etyp  = (const int*)d_in[8];
    float* out = (float*)d_out;

    int N = in_sizes[0] / HID;
    int E = in_sizes[8];
    if (N > MAXN) N = MAXN;
    int ntiles = (E + ETILE - 1) / ETILE;
    int Epad = ntiles * ETILE;
    if (Epad > MAXE) { Epad = MAXE; ntiles = Epad / ETILE; }

    float* h1 = nullptr;
    cudaGetSymbolAddress((void**)&h1, g_h1);

    const int EDGE_SMEM = (NREL * WSTRIDE + 2 * HID * XSTR) * 4 + 2 * 3 * ETILE * 4;
    const int INIT_SMEM = (GROWS * 101 + HID * HID) * 4;
    cudaFuncSetAttribute(k_edge, cudaFuncAttributeMaxDynamicSharedMemorySize, EDGE_SMEM);
    cudaFuncSetAttribute(k_init, cudaFuncAttributeMaxDynamicSharedMemorySize, INIT_SMEM);

    int RN = NREL * N;
    int nb = (N + 1023) / 1024;      // 98 blocks, all resident
    int init_grid = (N + GROWS - 1) / GROWS;
    const int EDGE_GRID = 148;

    // --- preprocessing (recomputed every call; graph-capturable) ---
    k_zero<<<(RN + 255) / 256, 256>>>(N, RN, E, Epad);
    k_count<<<(E + 255) / 256, 256>>>(eidx, etyp, E, N);
    k_scan<<<nb, 1024>>>(N);
    k_scatter<<<(E + 255) / 256, 256>>>(eidx, etyp, E, N);

    // --- layer 1: h1 = node_emb @ root1 + bias1 + block_agg(node_emb) ---
    k_init<<<init_grid, GTHREADS, INIT_SMEM>>>(node_emb, root1, bias1, h1, N);
    k_edge<<<EDGE_GRID, ETHREADS, EDGE_SMEM>>>(node_emb, w1, h1, ntiles);

    // --- relu in place ---
    k_relu<<<(N * HID + 511) / 512, 512>>>(h1, N * HID);

    // --- layer 2: out = relu(h1) @ root2 + bias2 + block_agg(relu(h1)) ---
    k_init<<<init_grid, GTHREADS, INIT_SMEM>>>(h1, root2, bias2, out, N);
    k_edge<<<EDGE_GRID, ETHREADS, EDGE_SMEM>>>(h1, w2, out, ntiles);
}

// round 9
// speedup vs baseline: 2.0356x; 1.4692x over previous
#include <cuda_runtime.h>
#include <cstdint>

#define HID      100
#define NREL     16
#define NBLK     5
#define CB       20
#define MAXN     100000
#define MAXE     1600128      // >= ntiles*ETILE for E=1.6M
#define WSTRIDE  2004         // per-relation weight stride (2000 used + 4 pad)
#define ETILE    96
#define ETHREADS 480          // 15 warps: b = t/96 (0..4), warp-uniform
#define RSTR     100          // res row stride (floats), 16B-aligned rows

// ---------------- scratch (device globals; no allocations allowed) ----------------
__device__ int   g_cnt[NREL * MAXN];     // per-(rel,dst) edge counts
__device__ int   g_hist[MAXN];           // per-dst edge counts (for sort)
__device__ int   g_cursor[MAXN];         // scatter cursors (exclusive prefix)
__device__ int   g_chain[256];           // lookback-scan chain (0 = not ready)
__device__ int4  g_edge[MAXE];           // dst-sorted edges: {src, dst, rel, scale-bits}
__device__ float g_h1[MAXN * HID];       // layer-1 output (pre-relu)

// ---------------- helpers ----------------
__device__ __forceinline__ uint32_t smaddr(const void* p) {
    return (uint32_t)__cvta_generic_to_shared(p);
}
__device__ __forceinline__ void cpa16(uint32_t s, const void* g) {
    asm volatile("cp.async.cg.shared.global [%0], [%1], 16;" :: "r"(s), "l"(g));
}
#define CPA_COMMIT() asm volatile("cp.async.commit_group;" ::: "memory")
#define CPA_WAIT1()  asm volatile("cp.async.wait_group 1;" ::: "memory")

// ---------------- setup kernels ----------------
__global__ void k_zero(int N, int RN, int E, int Epad) {
    int i = blockIdx.x * blockDim.x + threadIdx.x;
    if (i < RN)  g_cnt[i] = 0;
    if (i < N)   g_hist[i] = 0;
    if (i < 256) g_chain[i] = 0;
    if (i < Epad - E) {                 // pad tail edges: inert (scale 0)
        g_edge[E + i] = make_int4(0, 0, 0, 0);
    }
}

__global__ void k_count(const int* __restrict__ eidx, const int* __restrict__ etyp,
                        int E, int N) {
    int e = blockIdx.x * blockDim.x + threadIdx.x;
    if (e >= E) return;
    int dst = eidx[E + e];
    int rel = etyp[e];
    atomicAdd(&g_cnt[rel * N + dst], 1);
    atomicAdd(&g_hist[dst], 1);
}

// single-pass exclusive scan of g_hist -> g_cursor, decoupled chain.
__global__ void k_scan(int N) {
    __shared__ int sh[1024];
    __shared__ int s_prev;
    int t = threadIdx.x, blk = blockIdx.x;
    int i = blk * 1024 + t;
    int x = (i < N) ? g_hist[i] : 0;
    sh[t] = x;
    __syncthreads();
    for (int off = 1; off < 1024; off <<= 1) {
        int v = (t >= off) ? sh[t - off] : 0;
        __syncthreads();
        sh[t] += v;
        __syncthreads();
    }
    if (t == 0) {
        int prev = 0;
        if (blk > 0) {
            int v;
            do {
                v = atomicAdd(&g_chain[blk - 1], 0);
                if (v == 0) __nanosleep(60);
            } while (v == 0);
            prev = v - 1;
        }
        atomicExch(&g_chain[blk], prev + sh[1023] + 1);
        s_prev = prev;
    }
    __syncthreads();
    if (i < N) g_cursor[i] = s_prev + sh[t] - x;
}

__global__ void k_scatter(const int* __restrict__ eidx, const int* __restrict__ etyp,
                          int E, int N) {
    int e = blockIdx.x * blockDim.x + threadIdx.x;
    if (e >= E) return;
    int src = eidx[e];
    int dst = eidx[E + e];
    int rel = etyp[e];
    int p = atomicAdd(&g_cursor[dst], 1);
    int c = g_cnt[rel * N + dst];
    float sc = 1.0f / (float)(c > 1 ? c : 1);
    g_edge[p] = make_int4(src, dst, rel, __float_as_int(sc));
}

// ---------------- dense part: out = (relu?)x @ root + bias ----------------
#define GROWS 80
#define GTHREADS 256
__global__ __launch_bounds__(GTHREADS)
void k_init(const float* __restrict__ x, const float* __restrict__ root,
            const float* __restrict__ bias, float* __restrict__ out,
            int N, int do_relu) {
    extern __shared__ float sm_i[];
    float* xs = sm_i;                 // 80 * 101
    float* rs = sm_i + GROWS * 101;   // 100 * 100
    int t = threadIdx.x;
    int rowbase = blockIdx.x * GROWS;

    for (int i = t; i < HID * HID; i += GTHREADS) rs[i] = root[i];
    for (int i = t; i < GROWS * HID; i += GTHREADS) {
        int rr = i / HID, c = i - rr * HID;
        int row = rowbase + rr;
        float v = (row < N) ? x[row * HID + c] : 0.0f;
        if (do_relu) v = fmaxf(v, 0.0f);
        xs[rr * 101 + c] = v;
    }
    __syncthreads();
    if (t >= 250) return;

    int q = t % 25;
    int rg = t / 25;
    float4 b4 = *reinterpret_cast<const float4*>(bias + 4 * q);
    float acc[8][4];
#pragma unroll
    for (int i = 0; i < 8; i++) {
        acc[i][0] = b4.x; acc[i][1] = b4.y; acc[i][2] = b4.z; acc[i][3] = b4.w;
    }
#pragma unroll 4
    for (int k = 0; k < HID; k++) {
        float4 r4 = *reinterpret_cast<const float4*>(rs + k * HID + 4 * q);
#pragma unroll
        for (int i = 0; i < 8; i++) {
            float xv = xs[(rg * 8 + i) * 101 + k];
            acc[i][0] = fmaf(xv, r4.x, acc[i][0]);
            acc[i][1] = fmaf(xv, r4.y, acc[i][1]);
            acc[i][2] = fmaf(xv, r4.z, acc[i][2]);
            acc[i][3] = fmaf(xv, r4.w, acc[i][3]);
        }
    }
#pragma unroll
    for (int i = 0; i < 8; i++) {
        int row = rowbase + rg * 8 + i;
        if (row < N) {
            float4 o;
            o.x = acc[i][0]; o.y = acc[i][1]; o.z = acc[i][2]; o.w = acc[i][3];
            *reinterpret_cast<float4*>(out + row * HID + 4 * q) = o;
        }
    }
}

// ---------------- edge kernel ----------------
// Edges globally dst-sorted. Per tile of 96 edges (persistent blocks,
// meta double-buffered via cp.async):
//   1. warps 0-2: stable counting sort of the 96 slots by relation (sinv);
//      warps 3-5: build dst-segment list (segs) via ballot.
//   2. all 15 warps: thread (b, j) handles edge o=sinv[j]: x row slice via
//      5x LDG.128 (L2-resident), rel-grouped weight LDS (broadcast-friendly),
//      400 FMA, write scaled 20-vec to res[o].
//   3. warp per dst-segment: 25-lane float4 sum over res rows, one atomic
//      set per segment.
//   4. trailing __syncthreads: phase-3 reads of md must complete before the
//      next iteration's cp.async prefetch overwrites that buffer (this was
//      the R8 race).
__global__ __launch_bounds__(ETHREADS)
void k_edge(const float* __restrict__ x, const float* __restrict__ w,
            float* __restrict__ out, int ntiles, int do_relu) {
    extern __shared__ float sm_e[];
    float* ws   = sm_e;                             // 16*2004 floats
    float* res  = ws + NREL * WSTRIDE;              // 96*100 floats
    int4*  md0  = (int4*)(res + ETILE * RSTR);      // 96 int4
    int4*  md1  = md0 + ETILE;                      // 96 int4
    int*   sinv = (int*)(md1 + ETILE);              // 96
    int*   segs = sinv + ETILE;                     // 97
    int*   scnt = segs + ETILE + 1;                 // 48 (3 warps x 16 rels)
    int*   sbase= scnt + 48;                        // 48
    int*   swx  = sbase + 48;                       // 8: [0..2] head counts, [3..5] offsets, [6] nseg

    int t = threadIdx.x;
    int lane = t & 31;
    int wrp = t >> 5;

    for (int i = t; i < NREL * NBLK * CB * CB; i += ETHREADS) {
        int r = i / 2000;
        ws[r * WSTRIDE + (i - r * 2000)] = w[i];
    }
    if (t < 48) scnt[t] = 0;

    int b = t / ETILE;          // 0..4, warp-uniform (96 = 3 warps)
    int e = t - b * ETILE;      // 0..95

    int first = blockIdx.x;
    if (first < ntiles && t < ETILE)
        cpa16(smaddr(md0 + t), &g_edge[first * ETILE + t]);
    CPA_COMMIT();

    int parity = 0;
    for (int tile = first; tile < ntiles; tile += gridDim.x) {
        int nxt = tile + gridDim.x;
        int4* mdn = parity ? md0 : md1;
        if (nxt < ntiles && t < ETILE)
            cpa16(smaddr(mdn + t), &g_edge[nxt * ETILE + t]);
        CPA_COMMIT();
        CPA_WAIT1();
        __syncthreads();                      // md(cur) ready; scnt zeroed

        const int4* md = parity ? md1 : md0;

        // ---- phase 1a: relation histogram (warps 0-2) + head counts (warps 3-5) ----
        int myrel = 0, myrank = 0;
        if (t < ETILE) {
            myrel = md[t].z;
            unsigned m = __match_any_sync(0xFFFFFFFFu, myrel);
            myrank = __popc(m & ((1u << lane) - 1u));
            if ((int)(__ffs(m) - 1) == lane) scnt[wrp * 16 + myrel] = __popc(m);
        } else if (t < 2 * ETILE) {
            int p = t - ETILE;
            bool head = (p == 0) || (md[p - 1].y != md[p].y);
            unsigned bal = __ballot_sync(0xFFFFFFFFu, head);
            if (lane == 0) swx[wrp - 3] = __popc(bal);
        }
        __syncthreads();

        // ---- phase 1b: offsets ----
        if (t < 16) {
            int c0 = scnt[t], c1 = scnt[16 + t], c2 = scnt[32 + t];
            int tot = c0 + c1 + c2;
            int run = tot;
#pragma unroll
            for (int d = 1; d < 16; d <<= 1) {
                int v = __shfl_up_sync(0xFFFFu, run, d);
                if (lane >= d) run += v;
            }
            int off = run - tot;
            sbase[t] = off; sbase[16 + t] = off + c0; sbase[32 + t] = off + c0 + c1;
        }
        if (t == 32) {
            int a = swx[0], bb = swx[1], c = swx[2];
            int ns = a + bb + c;
            swx[3] = 0; swx[4] = a; swx[5] = a + bb; swx[6] = ns;
            segs[ns] = ETILE;   // sentinel
        }
        __syncthreads();

        // ---- phase 1c: scatter sinv + seg starts; re-zero scnt ----
        if (t < ETILE) {
            sinv[sbase[wrp * 16 + myrel] + myrank] = t;
        } else if (t < 2 * ETILE) {
            int p = t - ETILE;
            bool head = (p == 0) || (md[p - 1].y != md[p].y);
            unsigned bal = __ballot_sync(0xFFFFFFFFu, head);
            if (head) segs[swx[3 + (wrp - 3)] + __popc(bal & ((1u << lane) - 1u))] = p;
        } else if (t < 2 * ETILE + 48) {
            scnt[t - 2 * ETILE] = 0;
        }
        __syncthreads();                      // sinv + segs ready

        // ---- phase 2: transform (rel-grouped), write res[orig slot] ----
        {
            int o = sinv[e];
            int4 em = md[o];
            float sc = __int_as_float(em.w);
            const float4* xg = reinterpret_cast<const float4*>(
                x + (size_t)em.x * HID + b * CB);
            float4 xv4[5];
#pragma unroll
            for (int k = 0; k < 5; k++) xv4[k] = __ldg(xg + k);
            if (do_relu) {
#pragma unroll
                for (int k = 0; k < 5; k++) {
                    xv4[k].x = fmaxf(xv4[k].x, 0.0f);
                    xv4[k].y = fmaxf(xv4[k].y, 0.0f);
                    xv4[k].z = fmaxf(xv4[k].z, 0.0f);
                    xv4[k].w = fmaxf(xv4[k].w, 0.0f);
                }
            }
            const float* xv = reinterpret_cast<const float*>(xv4);
            const float* wb = ws + em.z * WSTRIDE + b * (CB * CB);
            float acc[CB];
#pragma unroll
            for (int d = 0; d < CB; d++) acc[d] = 0.0f;
#pragma unroll
            for (int c = 0; c < CB; c++) {
                float xvc = xv[c];
                const float4* w4 = reinterpret_cast<const float4*>(wb + c * CB);
#pragma unroll
                for (int d4 = 0; d4 < 5; d4++) {
                    float4 wv = w4[d4];
                    acc[4 * d4 + 0] = fmaf(xvc, wv.x, acc[4 * d4 + 0]);
                    acc[4 * d4 + 1] = fmaf(xvc, wv.y, acc[4 * d4 + 1]);
                    acc[4 * d4 + 2] = fmaf(xvc, wv.z, acc[4 * d4 + 2]);
                    acc[4 * d4 + 3] = fmaf(xvc, wv.w, acc[4 * d4 + 3]);
                }
            }
            float4* rp = reinterpret_cast<float4*>(res + o * RSTR + b * CB);
#pragma unroll
            for (int d4 = 0; d4 < 5; d4++) {
                float4 v;
                v.x = acc[4 * d4 + 0] * sc; v.y = acc[4 * d4 + 1] * sc;
                v.z = acc[4 * d4 + 2] * sc; v.w = acc[4 * d4 + 3] * sc;
                rp[d4] = v;
            }
        }
        __syncthreads();                      // res complete

        // ---- phase 3: per-segment sum + atomics (warp per segment) ----
        {
            int nseg = swx[6];
            for (int s = wrp; s < nseg; s += ETHREADS / 32) {
                int a0 = segs[s], a1 = segs[s + 1];
                if (lane < 25) {
                    float4 a4 = make_float4(0.0f, 0.0f, 0.0f, 0.0f);
                    for (int ee = a0; ee < a1; ee++) {
                        float4 v = *reinterpret_cast<const float4*>(
                            res + ee * RSTR + 4 * lane);
                        a4.x += v.x; a4.y += v.y; a4.z += v.z; a4.w += v.w;
                    }
                    float* op = out + (size_t)md[a0].y * HID + 4 * lane;
                    atomicAdd(op + 0, a4.x);
                    atomicAdd(op + 1, a4.y);
                    atomicAdd(op + 2, a4.z);
                    atomicAdd(op + 3, a4.w);
                }
            }
        }
        __syncthreads();   // R8 race fix: md readers done before next prefetch
        parity ^= 1;
    }
}

// ---------------- host launcher ----------------
extern "C" void kernel_launch(void* const* d_in, const int* in_sizes, int n_in,
                              void* d_out, int out_size) {
    const float* node_emb = (const float*)d_in[0];
    const float* w1    = (const float*)d_in[1];
    const float* root1 = (const float*)d_in[2];
    const float* bias1 = (const float*)d_in[3];
    const float* w2    = (const float*)d_in[4];
    const float* root2 = (const float*)d_in[5];
    const float* bias2 = (const float*)d_in[6];
    const int*   eidx  = (const int*)d_in[7];
    const int*   etyp  = (const int*)d_in[8];
    float* out = (float*)d_out;

    int N = in_sizes[0] / HID;
    int E = in_sizes[8];
    if (N > MAXN) N = MAXN;
    int ntiles = (E + ETILE - 1) / ETILE;
    int Epad = ntiles * ETILE;
    if (Epad > MAXE) { Epad = MAXE; ntiles = Epad / ETILE; }

    float* h1 = nullptr;
    cudaGetSymbolAddress((void**)&h1, g_h1);

    const int EDGE_SMEM = (NREL * WSTRIDE + ETILE * RSTR) * 4      // ws + res
                        + 2 * ETILE * 16                            // md0, md1
                        + (ETILE + ETILE + 1 + 48 + 48 + 8) * 4;    // sinv/segs/scnt/sbase/swx
    const int INIT_SMEM = (GROWS * 101 + HID * HID) * 4;
    cudaFuncSetAttribute(k_edge, cudaFuncAttributeMaxDynamicSharedMemorySize, EDGE_SMEM);
    cudaFuncSetAttribute(k_init, cudaFuncAttributeMaxDynamicSharedMemorySize, INIT_SMEM);

    int RN = NREL * N;
    int nb = (N + 1023) / 1024;      // 98 blocks, all resident
    int init_grid = (N + GROWS - 1) / GROWS;
    const int EDGE_GRID = 148;

    // --- preprocessing (recomputed every call; graph-capturable) ---
    k_zero<<<(RN + 255) / 256, 256>>>(N, RN, E, Epad);
    k_count<<<(E + 255) / 256, 256>>>(eidx, etyp, E, N);
    k_scan<<<nb, 1024>>>(N);
    k_scatter<<<(E + 255) / 256, 256>>>(eidx, etyp, E, N);

    // --- layer 1: h1 = node_emb @ root1 + bias1 + block_agg(node_emb) ---
    k_init<<<init_grid, GTHREADS, INIT_SMEM>>>(node_emb, root1, bias1, h1, N, 0);
    k_edge<<<EDGE_GRID, ETHREADS, EDGE_SMEM>>>(node_emb, w1, h1, ntiles, 0);

    // --- layer 2: out = relu(h1) @ root2 + bias2 + block_agg(relu(h1)) ---
    k_init<<<init_grid, GTHREADS, INIT_SMEM>>>(h1, root2, bias2, out, N, 1);
    k_edge<<<EDGE_GRID, ETHREADS, EDGE_SMEM>>>(h1, w2, out, ntiles, 1);
}

// round 10
// speedup vs baseline: 2.0883x; 1.0259x over previous
#include <cuda_runtime.h>
#include <cstdint>

#define HID      100
#define NREL     16
#define NBLK     5
#define CB       20
#define MAXN     100000
#define MAXE     1600128      // >= ntiles*ETILE for E=1.6M
#define WSTRIDE  2004         // per-relation weight stride (2000 used + 4 pad)
#define ETILE    128
#define ETHREADS 640          // 20 warps: b = t/128 (0..4), warp-uniform
#define RSTR     100          // res row stride (floats)

// ---------------- scratch (device globals; no allocations allowed) ----------------
__device__ int   g_cnt[NREL * MAXN];     // per-(rel,dst) edge counts
__device__ int   g_hist[MAXN];           // per-dst edge counts (for sort)
__device__ int   g_cursor[MAXN];         // scatter cursors (exclusive prefix)
__device__ int   g_chain[256];           // lookback-scan chain (0 = not ready)
__device__ int4  g_edge[MAXE];           // dst-sorted edges: {src, dst, rel, scale-bits}
__device__ float g_h1[MAXN * HID];       // layer-1 output (pre-relu)

// ---------------- helpers ----------------
__device__ __forceinline__ uint32_t smaddr(const void* p) {
    return (uint32_t)__cvta_generic_to_shared(p);
}
__device__ __forceinline__ void cpa16(uint32_t s, const void* g) {
    asm volatile("cp.async.cg.shared.global [%0], [%1], 16;" :: "r"(s), "l"(g));
}
#define CPA_COMMIT() asm volatile("cp.async.commit_group;" ::: "memory")
#define CPA_WAIT0()  asm volatile("cp.async.wait_group 0;" ::: "memory")

// ---------------- setup kernels ----------------
__global__ void k_zero(int N, int RN, int E, int Epad) {
    int i = blockIdx.x * blockDim.x + threadIdx.x;
    if (i < RN)  g_cnt[i] = 0;
    if (i < N)   g_hist[i] = 0;
    if (i < 256) g_chain[i] = 0;
    if (i < Epad - E) {                 // pad tail edges: inert (scale 0)
        g_edge[E + i] = make_int4(0, 0, 0, 0);
    }
}

__global__ void k_count(const int* __restrict__ eidx, const int* __restrict__ etyp,
                        int E, int N) {
    int e = blockIdx.x * blockDim.x + threadIdx.x;
    if (e >= E) return;
    int dst = eidx[E + e];
    int rel = etyp[e];
    atomicAdd(&g_cnt[rel * N + dst], 1);
    atomicAdd(&g_hist[dst], 1);
}

// single-pass exclusive scan of g_hist -> g_cursor, decoupled chain.
__global__ void k_scan(int N) {
    __shared__ int sh[1024];
    __shared__ int s_prev;
    int t = threadIdx.x, blk = blockIdx.x;
    int i = blk * 1024 + t;
    int x = (i < N) ? g_hist[i] : 0;
    sh[t] = x;
    __syncthreads();
    for (int off = 1; off < 1024; off <<= 1) {
        int v = (t >= off) ? sh[t - off] : 0;
        __syncthreads();
        sh[t] += v;
        __syncthreads();
    }
    if (t == 0) {
        int prev = 0;
        if (blk > 0) {
            int v;
            do {
                v = atomicAdd(&g_chain[blk - 1], 0);
                if (v == 0) __nanosleep(60);
            } while (v == 0);
            prev = v - 1;
        }
        atomicExch(&g_chain[blk], prev + sh[1023] + 1);
        s_prev = prev;
    }
    __syncthreads();
    if (i < N) g_cursor[i] = s_prev + sh[t] - x;
}

__global__ void k_scatter(const int* __restrict__ eidx, const int* __restrict__ etyp,
                          int E, int N) {
    int e = blockIdx.x * blockDim.x + threadIdx.x;
    if (e >= E) return;
    int src = eidx[e];
    int dst = eidx[E + e];
    int rel = etyp[e];
    int p = atomicAdd(&g_cursor[dst], 1);
    int c = g_cnt[rel * N + dst];
    float sc = 1.0f / (float)(c > 1 ? c : 1);
    g_edge[p] = make_int4(src, dst, rel, __float_as_int(sc));
}

// ---------------- dense part: out = (relu?)x @ root + bias ----------------
#define GROWS 80
#define GTHREADS 256
__global__ __launch_bounds__(GTHREADS)
void k_init(const float* __restrict__ x, const float* __restrict__ root,
            const float* __restrict__ bias, float* __restrict__ out,
            int N, int do_relu) {
    extern __shared__ float sm_i[];
    float* xs = sm_i;                 // 80 * 101
    float* rs = sm_i + GROWS * 101;   // 100 * 100
    int t = threadIdx.x;
    int rowbase = blockIdx.x * GROWS;

    for (int i = t; i < HID * HID; i += GTHREADS) rs[i] = root[i];
    for (int i = t; i < GROWS * HID; i += GTHREADS) {
        int rr = i / HID, c = i - rr * HID;
        int row = rowbase + rr;
        float v = (row < N) ? x[row * HID + c] : 0.0f;
        if (do_relu) v = fmaxf(v, 0.0f);
        xs[rr * 101 + c] = v;
    }
    __syncthreads();
    if (t >= 250) return;

    int q = t % 25;
    int rg = t / 25;
    float4 b4 = *reinterpret_cast<const float4*>(bias + 4 * q);
    float acc[8][4];
#pragma unroll
    for (int i = 0; i < 8; i++) {
        acc[i][0] = b4.x; acc[i][1] = b4.y; acc[i][2] = b4.z; acc[i][3] = b4.w;
    }
#pragma unroll 4
    for (int k = 0; k < HID; k++) {
        float4 r4 = *reinterpret_cast<const float4*>(rs + k * HID + 4 * q);
#pragma unroll
        for (int i = 0; i < 8; i++) {
            float xv = xs[(rg * 8 + i) * 101 + k];
            acc[i][0] = fmaf(xv, r4.x, acc[i][0]);
            acc[i][1] = fmaf(xv, r4.y, acc[i][1]);
            acc[i][2] = fmaf(xv, r4.z, acc[i][2]);
            acc[i][3] = fmaf(xv, r4.w, acc[i][3]);
        }
    }
#pragma unroll
    for (int i = 0; i < 8; i++) {
        int row = rowbase + rg * 8 + i;
        if (row < N) {
            float4 o;
            o.x = acc[i][0]; o.y = acc[i][1]; o.z = acc[i][2]; o.w = acc[i][3];
            *reinterpret_cast<float4*>(out + row * HID + 4 * q) = o;
        }
    }
}

// ---------------- edge kernel (software-pipelined) ----------------
// Per iteration (tile t):
//   phase2: transform tile t (x pre-loaded in regs last iter) -> res
//   wait meta(t+1); sort t+1 (rel counting-sort + dst segments, dbl-buffered)
//   issue x LDGs for t+1 into registers (overlap with phase 3)
//   phase3: per-dst-segment sum over res + atomics (tile t)
//   prefetch meta(t+2)

// in-tile sort: warps 0-3 rel histogram, warps 4-7 dst-segment heads.
__device__ __forceinline__ void sort_tile(const int4* md, int* sinv, int* segs,
                                          int* scnt, int* sbase, int* swx,
                                          int t, int lane, int wrp) {
    int myrel = 0, myrank = 0;
    if (t < ETILE) {
        myrel = md[t].z;
        unsigned m = __match_any_sync(0xFFFFFFFFu, myrel);
        myrank = __popc(m & ((1u << lane) - 1u));
        if ((int)(__ffs(m) - 1) == lane) scnt[wrp * 16 + myrel] = __popc(m);
    } else if (t < 2 * ETILE) {
        int p = t - ETILE;
        bool head = (p == 0) || (md[p - 1].y != md[p].y);
        unsigned bal = __ballot_sync(0xFFFFFFFFu, head);
        if (lane == 0) swx[wrp - 4] = __popc(bal);
    }
    __syncthreads();
    if (t < 16) {
        int c0 = scnt[t], c1 = scnt[16 + t], c2 = scnt[32 + t], c3 = scnt[48 + t];
        int tot = c0 + c1 + c2 + c3;
        int run = tot;
#pragma unroll
        for (int d = 1; d < 16; d <<= 1) {
            int v = __shfl_up_sync(0xFFFFu, run, d);
            if (lane >= d) run += v;
        }
        int off = run - tot;
        sbase[t]      = off;
        sbase[16 + t] = off + c0;
        sbase[32 + t] = off + c0 + c1;
        sbase[48 + t] = off + c0 + c1 + c2;
    }
    if (t == 256) {
        int a = swx[0], b2 = swx[1], c = swx[2], d = swx[3];
        int ns = a + b2 + c + d;
        swx[4] = 0; swx[5] = a; swx[6] = a + b2; swx[7] = a + b2 + c;
        swx[8] = ns;
        segs[ns] = ETILE;   // sentinel
    }
    __syncthreads();
    if (t < ETILE) {
        sinv[sbase[wrp * 16 + myrel] + myrank] = t;
    } else if (t < 2 * ETILE) {
        int p = t - ETILE;
        bool head = (p == 0) || (md[p - 1].y != md[p].y);
        unsigned bal = __ballot_sync(0xFFFFFFFFu, head);
        if (head) segs[swx[4 + (wrp - 4)] + __popc(bal & ((1u << lane) - 1u))] = p;
    } else if (t < 2 * ETILE + 64) {
        scnt[t - 2 * ETILE] = 0;   // re-zero for next sort
    }
    __syncthreads();
}

__global__ __launch_bounds__(ETHREADS)
void k_edge(const float* __restrict__ x, const float* __restrict__ w,
            float* __restrict__ out, int ntiles, int do_relu) {
    extern __shared__ float sm_e[];
    float* ws    = sm_e;                            // 16*2004 floats
    float* res   = ws + NREL * WSTRIDE;             // 128*100 floats
    int4*  md0   = (int4*)(res + ETILE * RSTR);     // 128 int4 (16B aligned)
    int4*  md1   = md0 + ETILE;                     // 128 int4
    int*   sinv0 = (int*)(md1 + ETILE);             // 128
    int*   sinv1 = sinv0 + ETILE;                   // 128
    int*   segs0 = sinv1 + ETILE;                   // 129
    int*   segs1 = segs0 + ETILE + 1;               // 129
    int*   scnt  = segs1 + ETILE + 1;               // 64 (4 warps x 16 rels)
    int*   sbase = scnt + 64;                       // 64
    int*   swx   = sbase + 64;                      // 16: [0..3] counts, [4..7] offs, [8] nseg

    int t = threadIdx.x;
    int lane = t & 31;
    int wrp = t >> 5;
    int b = t >> 7;             // 0..4, warp-uniform
    int e = t & (ETILE - 1);    // 0..127

    for (int i = t; i < NREL * NBLK * CB * CB; i += ETHREADS) {
        int r = i / 2000;
        ws[r * WSTRIDE + (i - r * 2000)] = w[i];
    }
    if (t < 64) scnt[t] = 0;

    int grid = gridDim.x;
    int tile0 = blockIdx.x;     // always < ntiles (grid 148 << 12500)

    // ---- pre-loop: load meta(tile0), sort it, prefetch x(tile0), issue meta(tile0+g) ----
    if (t < ETILE) cpa16(smaddr(md0 + t), &g_edge[(size_t)tile0 * ETILE + t]);
    CPA_COMMIT();
    CPA_WAIT0();
    __syncthreads();            // md0 + ws + scnt ready

    sort_tile(md0, sinv0, segs0, scnt, sbase, swx, t, lane, wrp);

    int   o_cur, rel_cur;
    float sc_cur;
    float4 xr[5];
    {
        o_cur = sinv0[e];
        int4 em = md0[o_cur];
        rel_cur = em.z;
        sc_cur = __int_as_float(em.w);
        const float4* xg = reinterpret_cast<const float4*>(
            x + (size_t)em.x * HID + b * CB);
#pragma unroll
        for (int k = 0; k < 5; k++) xr[k] = __ldg(xg + k);
        if (do_relu) {
#pragma unroll
            for (int k = 0; k < 5; k++) {
                xr[k].x = fmaxf(xr[k].x, 0.0f); xr[k].y = fmaxf(xr[k].y, 0.0f);
                xr[k].z = fmaxf(xr[k].z, 0.0f); xr[k].w = fmaxf(xr[k].w, 0.0f);
            }
        }
    }
    if (tile0 + grid < ntiles && t < ETILE)
        cpa16(smaddr(md1 + t), &g_edge[(size_t)(tile0 + grid) * ETILE + t]);
    CPA_COMMIT();

    int par = 0;
    for (int tile = tile0; tile < ntiles; tile += grid) {
        int nxt = tile + grid;
        const int4* mdc  = par ? md1 : md0;
        const int4* mdn  = par ? md0 : md1;
        int* sinvn = par ? sinv0 : sinv1;
        int* segsc = par ? segs1 : segs0;
        int* segsn = par ? segs0 : segs1;

        // ---- phase 2: transform tile (cur) from registers ----
        {
            const float* xv = reinterpret_cast<const float*>(xr);
            const float* wb = ws + rel_cur * WSTRIDE + b * (CB * CB);
            float acc[CB];
#pragma unroll
            for (int d = 0; d < CB; d++) acc[d] = 0.0f;
#pragma unroll
            for (int c = 0; c < CB; c++) {
                float xvc = xv[c];
                const float4* w4 = reinterpret_cast<const float4*>(wb + c * CB);
#pragma unroll
                for (int d4 = 0; d4 < 5; d4++) {
                    float4 wv = w4[d4];
                    acc[4 * d4 + 0] = fmaf(xvc, wv.x, acc[4 * d4 + 0]);
                    acc[4 * d4 + 1] = fmaf(xvc, wv.y, acc[4 * d4 + 1]);
                    acc[4 * d4 + 2] = fmaf(xvc, wv.z, acc[4 * d4 + 2]);
                    acc[4 * d4 + 3] = fmaf(xvc, wv.w, acc[4 * d4 + 3]);
                }
            }
            float4* rp = reinterpret_cast<float4*>(res + o_cur * RSTR + b * CB);
#pragma unroll
            for (int d4 = 0; d4 < 5; d4++) {
                float4 v;
                v.x = acc[4 * d4 + 0] * sc_cur; v.y = acc[4 * d4 + 1] * sc_cur;
                v.z = acc[4 * d4 + 2] * sc_cur; v.w = acc[4 * d4 + 3] * sc_cur;
                rp[d4] = v;
            }
        }

        int nseg_cur = swx[8];        // snapshot before next sort overwrites

        CPA_WAIT0();                  // meta(nxt) arrived
        __syncthreads();              // res complete; mdn visible

        // ---- sort tile (nxt) ----
        sort_tile(mdn, sinvn, segsn, scnt, sbase, swx, t, lane, wrp);

        // ---- prefetch x for (nxt) into registers ----
        if (nxt < ntiles) {
            o_cur = sinvn[e];
            int4 em = mdn[o_cur];
            rel_cur = em.z;
            sc_cur = __int_as_float(em.w);
            const float4* xg = reinterpret_cast<const float4*>(
                x + (size_t)em.x * HID + b * CB);
#pragma unroll
            for (int k = 0; k < 5; k++) xr[k] = __ldg(xg + k);
            if (do_relu) {
#pragma unroll
                for (int k = 0; k < 5; k++) {
                    xr[k].x = fmaxf(xr[k].x, 0.0f); xr[k].y = fmaxf(xr[k].y, 0.0f);
                    xr[k].z = fmaxf(xr[k].z, 0.0f); xr[k].w = fmaxf(xr[k].w, 0.0f);
                }
            }
        }

        // ---- phase 3: per-segment sum + atomics for tile (cur) ----
        for (int s = wrp; s < nseg_cur; s += ETHREADS / 32) {
            int a0 = segsc[s], a1 = segsc[s + 1];
            if (lane < 25) {
                float4 a4 = make_float4(0.0f, 0.0f, 0.0f, 0.0f);
                for (int ee = a0; ee < a1; ee++) {
                    float4 v = *reinterpret_cast<const float4*>(
                        res + ee * RSTR + 4 * lane);
                    a4.x += v.x; a4.y += v.y; a4.z += v.z; a4.w += v.w;
                }
                float* op = out + (size_t)mdc[a0].y * HID + 4 * lane;
                atomicAdd(op + 0, a4.x);
                atomicAdd(op + 1, a4.y);
                atomicAdd(op + 2, a4.z);
                atomicAdd(op + 3, a4.w);
            }
        }
        __syncthreads();              // mdc/res readers done before rewrite

        // ---- prefetch meta(tile + 2*grid) into mdc's buffer ----
        if (tile + 2 * grid < ntiles && t < ETILE) {
            int4* dstbuf = par ? md1 : md0;
            cpa16(smaddr(dstbuf + t), &g_edge[(size_t)(tile + 2 * grid) * ETILE + t]);
        }
        CPA_COMMIT();
        par ^= 1;
    }
}

// ---------------- host launcher ----------------
extern "C" void kernel_launch(void* const* d_in, const int* in_sizes, int n_in,
                              void* d_out, int out_size) {
    const float* node_emb = (const float*)d_in[0];
    const float* w1    = (const float*)d_in[1];
    const float* root1 = (const float*)d_in[2];
    const float* bias1 = (const float*)d_in[3];
    const float* w2    = (const float*)d_in[4];
    const float* root2 = (const float*)d_in[5];
    const float* bias2 = (const float*)d_in[6];
    const int*   eidx  = (const int*)d_in[7];
    const int*   etyp  = (const int*)d_in[8];
    float* out = (float*)d_out;

    int N = in_sizes[0] / HID;
    int E = in_sizes[8];
    if (N > MAXN) N = MAXN;
    int ntiles = (E + ETILE - 1) / ETILE;
    int Epad = ntiles * ETILE;
    if (Epad > MAXE) { Epad = MAXE; ntiles = Epad / ETILE; }

    float* h1 = nullptr;
    cudaGetSymbolAddress((void**)&h1, g_h1);

    const int EDGE_SMEM = (NREL * WSTRIDE + ETILE * RSTR) * 4      // ws + res
                        + 2 * ETILE * 16                            // md0, md1
                        + (2 * ETILE + 2 * (ETILE + 1) + 64 + 64 + 16) * 4;
    const int INIT_SMEM = (GROWS * 101 + HID * HID) * 4;
    cudaFuncSetAttribute(k_edge, cudaFuncAttributeMaxDynamicSharedMemorySize, EDGE_SMEM);
    cudaFuncSetAttribute(k_init, cudaFuncAttributeMaxDynamicSharedMemorySize, INIT_SMEM);

    int RN = NREL * N;
    int nb = (N + 1023) / 1024;      // 98 blocks, all resident
    int init_grid = (N + GROWS - 1) / GROWS;
    const int EDGE_GRID = 148;

    // --- preprocessing (recomputed every call; graph-capturable) ---
    k_zero<<<(RN + 255) / 256, 256>>>(N, RN, E, Epad);
    k_count<<<(E + 255) / 256, 256>>>(eidx, etyp, E, N);
    k_scan<<<nb, 1024>>>(N);
    k_scatter<<<(E + 255) / 256, 256>>>(eidx, etyp, E, N);

    // --- layer 1: h1 = node_emb @ root1 + bias1 + block_agg(node_emb) ---
    k_init<<<init_grid, GTHREADS, INIT_SMEM>>>(node_emb, root1, bias1, h1, N, 0);
    k_edge<<<EDGE_GRID, ETHREADS, EDGE_SMEM>>>(node_emb, w1, h1, ntiles, 0);

    // --- layer 2: out = relu(h1) @ root2 + bias2 + block_agg(relu(h1)) ---
    k_init<<<init_grid, GTHREADS, INIT_SMEM>>>(h1, root2, bias2, out, N, 1);
    k_edge<<<EDGE_GRID, ETHREADS, EDGE_SMEM>>>(h1, w2, out, ntiles, 1);
}

// round 11
// speedup vs baseline: 2.1771x; 1.0425x over previous
#include <cuda_runtime.h>
#include <cstdint>

#define HID      100
#define NREL     16
#define NBLK     5
#define CB       20
#define MAXN     100000
#define MAXE     1600128      // >= ntiles*ETILE for E=1.6M
#define WSTRIDE  2004         // per-relation weight stride (2000 used + 4 pad)
#define ETILE    96
#define ETHREADS 480          // 15 warps: b = t/96 (0..4), warp-uniform

// ---------------- scratch (device globals; no allocations allowed) ----------------
__device__ int   g_cnt[NREL * MAXN];     // per-(rel,dst) edge counts
__device__ int   g_hist[MAXN];           // per-dst edge counts (for sort)
__device__ int   g_cursor[MAXN];         // scatter cursors (exclusive prefix)
__device__ int   g_chain[256];           // lookback-scan chain (0 = not ready)
__device__ int4  g_edge[MAXE];           // dst-sorted edges: {src, dst, rel, scale-bits}
__device__ float g_h1[MAXN * HID];       // layer-1 output (pre-relu)

// ---------------- helpers ----------------
__device__ __forceinline__ uint32_t smaddr(const void* p) {
    return (uint32_t)__cvta_generic_to_shared(p);
}
__device__ __forceinline__ void cpa16(uint32_t s, const void* g) {
    asm volatile("cp.async.cg.shared.global [%0], [%1], 16;" :: "r"(s), "l"(g));
}
#define CPA_COMMIT() asm volatile("cp.async.commit_group;" ::: "memory")
#define CPA_WAIT0()  asm volatile("cp.async.wait_group 0;" ::: "memory")

// ---------------- setup kernels ----------------
__global__ void k_zero(int N, int RN, int E, int Epad) {
    int i = blockIdx.x * blockDim.x + threadIdx.x;
    if (i < RN)  g_cnt[i] = 0;
    if (i < N)   g_hist[i] = 0;
    if (i < 256) g_chain[i] = 0;
    if (i < Epad - E) {                 // pad tail edges: inert (scale 0)
        g_edge[E + i] = make_int4(0, 0, 0, 0);
    }
}

__global__ void k_count(const int* __restrict__ eidx, const int* __restrict__ etyp,
                        int E, int N) {
    int e = blockIdx.x * blockDim.x + threadIdx.x;
    if (e >= E) return;
    int dst = eidx[E + e];
    int rel = etyp[e];
    atomicAdd(&g_cnt[rel * N + dst], 1);
    atomicAdd(&g_hist[dst], 1);
}

// single-pass exclusive scan of g_hist -> g_cursor, decoupled chain.
__global__ void k_scan(int N) {
    __shared__ int sh[1024];
    __shared__ int s_prev;
    int t = threadIdx.x, blk = blockIdx.x;
    int i = blk * 1024 + t;
    int x = (i < N) ? g_hist[i] : 0;
    sh[t] = x;
    __syncthreads();
    for (int off = 1; off < 1024; off <<= 1) {
        int v = (t >= off) ? sh[t - off] : 0;
        __syncthreads();
        sh[t] += v;
        __syncthreads();
    }
    if (t == 0) {
        int prev = 0;
        if (blk > 0) {
            int v;
            do {
                v = atomicAdd(&g_chain[blk - 1], 0);
                if (v == 0) __nanosleep(60);
            } while (v == 0);
            prev = v - 1;
        }
        atomicExch(&g_chain[blk], prev + sh[1023] + 1);
        s_prev = prev;
    }
    __syncthreads();
    if (i < N) g_cursor[i] = s_prev + sh[t] - x;
}

__global__ void k_scatter(const int* __restrict__ eidx, const int* __restrict__ etyp,
                          int E, int N) {
    int e = blockIdx.x * blockDim.x + threadIdx.x;
    if (e >= E) return;
    int src = eidx[e];
    int dst = eidx[E + e];
    int rel = etyp[e];
    int p = atomicAdd(&g_cursor[dst], 1);
    int c = g_cnt[rel * N + dst];
    float sc = 1.0f / (float)(c > 1 ? c : 1);
    g_edge[p] = make_int4(src, dst, rel, __float_as_int(sc));
}

// ---------------- dense part: out = (relu?)x @ root + bias ----------------
#define GROWS 80
#define GTHREADS 256
__global__ __launch_bounds__(GTHREADS)
void k_init(const float* __restrict__ x, const float* __restrict__ root,
            const float* __restrict__ bias, float* __restrict__ out,
            int N, int do_relu) {
    extern __shared__ float sm_i[];
    float* xs = sm_i;                 // 80 * 101
    float* rs = sm_i + GROWS * 101;   // 100 * 100
    int t = threadIdx.x;
    int rowbase = blockIdx.x * GROWS;

    for (int i = t; i < HID * HID; i += GTHREADS) rs[i] = root[i];
    for (int i = t; i < GROWS * HID; i += GTHREADS) {
        int rr = i / HID, c = i - rr * HID;
        int row = rowbase + rr;
        float v = (row < N) ? x[row * HID + c] : 0.0f;
        if (do_relu) v = fmaxf(v, 0.0f);
        xs[rr * 101 + c] = v;
    }
    __syncthreads();
    if (t >= 250) return;

    int q = t % 25;
    int rg = t / 25;
    float4 b4 = *reinterpret_cast<const float4*>(bias + 4 * q);
    float acc[8][4];
#pragma unroll
    for (int i = 0; i < 8; i++) {
        acc[i][0] = b4.x; acc[i][1] = b4.y; acc[i][2] = b4.z; acc[i][3] = b4.w;
    }
#pragma unroll 4
    for (int k = 0; k < HID; k++) {
        float4 r4 = *reinterpret_cast<const float4*>(rs + k * HID + 4 * q);
#pragma unroll
        for (int i = 0; i < 8; i++) {
            float xv = xs[(rg * 8 + i) * 101 + k];
            acc[i][0] = fmaf(xv, r4.x, acc[i][0]);
            acc[i][1] = fmaf(xv, r4.y, acc[i][1]);
            acc[i][2] = fmaf(xv, r4.z, acc[i][2]);
            acc[i][3] = fmaf(xv, r4.w, acc[i][3]);
        }
    }
#pragma unroll
    for (int i = 0; i < 8; i++) {
        int row = rowbase + rg * 8 + i;
        if (row < N) {
            float4 o;
            o.x = acc[i][0]; o.y = acc[i][1]; o.z = acc[i][2]; o.w = acc[i][3];
            *reinterpret_cast<float4*>(out + row * HID + 4 * q) = o;
        }
    }
}

// ---------------- edge kernel ----------------
// Per tile of 96 dst-sorted edges:
//   sort by relation (warps 0-2) + dst-segment list (warps 3-5); fwd/sinv maps.
//   x rows staged by cp.async 16B in SORTED order into xs (stride 100, rows
//   16B-aligned) -> compute LDS.128 conflict-free, staging line-coalesced.
//   phase2: thread (b,e) transforms sorted row e, writes scaled result
//   IN PLACE (each (row, col-block) cell touched by exactly one thread).
//   phase3: warp per dst-segment sums rows via fwd[] + 4 atomics per 25 lanes.
// Pipeline: meta triple-buffered; x double-buffered; sort+stage of t+1 and
// meta prefetch of t+2 issued before phase2(t) so cp.async latency hides
// behind compute.

__device__ __forceinline__ void sort_tile96(const int4* md, int* sinv, int* fwd,
                                            int* srl, float* ssc, int* segs,
                                            int* scnt, int* sbase, int* swx,
                                            int t, int lane, int wrp) {
    int myrel = 0, myrank = 0;
    if (t < ETILE) {
        myrel = md[t].z;
        unsigned m = __match_any_sync(0xFFFFFFFFu, myrel);
        myrank = __popc(m & ((1u << lane) - 1u));
        if ((int)(__ffs(m) - 1) == lane) scnt[wrp * 16 + myrel] = __popc(m);
    } else if (t < 2 * ETILE) {
        int p = t - ETILE;
        bool head = (p == 0) || (md[p - 1].y != md[p].y);
        unsigned bal = __ballot_sync(0xFFFFFFFFu, head);
        if (lane == 0) swx[wrp - 3] = __popc(bal);
    }
    __syncthreads();
    if (t < 16) {
        int c0 = scnt[t], c1 = scnt[16 + t], c2 = scnt[32 + t];
        int tot = c0 + c1 + c2;
        int run = tot;
#pragma unroll
        for (int d = 1; d < 16; d <<= 1) {
            int v = __shfl_up_sync(0xFFFFu, run, d);
            if (lane >= d) run += v;
        }
        int off = run - tot;
        sbase[t]      = off;
        sbase[16 + t] = off + c0;
        sbase[32 + t] = off + c0 + c1;
    }
    if (t == 2 * ETILE) {
        int a = swx[0], b2 = swx[1], c = swx[2];
        int ns = a + b2 + c;
        swx[3] = 0; swx[4] = a; swx[5] = a + b2; swx[6] = ns;
        segs[ns] = ETILE;   // sentinel
    }
    __syncthreads();
    if (t < ETILE) {
        int pos = sbase[wrp * 16 + myrel] + myrank;
        sinv[pos] = t;
        fwd[t] = pos;
        srl[pos] = myrel;
        ssc[pos] = __int_as_float(md[t].w);
    } else if (t < 2 * ETILE) {
        int p = t - ETILE;
        bool head = (p == 0) || (md[p - 1].y != md[p].y);
        unsigned bal = __ballot_sync(0xFFFFFFFFu, head);
        if (head) segs[swx[3 + (wrp - 3)] + __popc(bal & ((1u << lane) - 1u))] = p;
    } else if (t < 2 * ETILE + 48) {
        scnt[t - 2 * ETILE] = 0;   // re-zero for next sort
    }
    __syncthreads();
}

// stage x rows of a tile into xs in SORTED order (row j holds edge sinv[j]).
// 96 rows x 25 float4 = 2400 cp.async.cg 16B, 5 per thread, line-coalesced.
__device__ __forceinline__ void stage_x(const float* __restrict__ x, const int4* md,
                                        const int* sinv, float* xs, int t) {
#pragma unroll
    for (int k = 0; k < (ETILE * 25) / ETHREADS; k++) {   // 5
        int idx = t + k * ETHREADS;
        int j = idx / 25, c4 = idx - j * 25;
        int src = md[sinv[j]].x;
        cpa16(smaddr(xs + j * 100 + c4 * 4), x + (size_t)src * HID + c4 * 4);
    }
}

__global__ __launch_bounds__(ETHREADS)
void k_edge(const float* __restrict__ x, const float* __restrict__ w,
            float* __restrict__ out, int ntiles, int do_relu) {
    extern __shared__ float sm_e[];
    float* ws    = sm_e;                               // 16*2004 = 32064 floats
    float* xs0   = ws + NREL * WSTRIDE;                // 96*100 (16B-aligned base)
    float* xs1   = xs0 + ETILE * 100;                  // 96*100
    int4*  mds0  = (int4*)(xs1 + ETILE * 100);         // 3 * 96 int4 (16B-aligned)
    int*   sinv0 = (int*)(mds0 + 3 * ETILE);
    int*   sinv1 = sinv0 + ETILE;
    int*   fwd0  = sinv1 + ETILE;
    int*   fwd1  = fwd0 + ETILE;
    int*   srl0  = fwd1 + ETILE;
    int*   srl1  = srl0 + ETILE;
    float* ssc0  = (float*)(srl1 + ETILE);
    float* ssc1  = ssc0 + ETILE;
    int*   segs0 = (int*)(ssc1 + ETILE);               // 97
    int*   segs1 = segs0 + ETILE + 1;                  // 97
    int*   scnt  = segs1 + ETILE + 1;                  // 48
    int*   sbase = scnt + 48;                          // 48
    int*   swx   = sbase + 48;                         // 8

    int t = threadIdx.x;
    int lane = t & 31;
    int wrp = t >> 5;
    int b = t / ETILE;          // 0..4, warp-uniform (96 = 3 warps)
    int e = t - b * ETILE;      // 0..95

    for (int i = t; i < NREL * 2000; i += ETHREADS) {
        int r = i / 2000;
        ws[r * WSTRIDE + (i - r * 2000)] = w[i];
    }
    if (t < 48) scnt[t] = 0;

    int grid = gridDim.x;
    int tile0 = blockIdx.x;

    // ---- preloop: meta(t0) -> sort -> stage x(t0); prefetch meta(t0+g) ----
    if (t < ETILE) cpa16(smaddr(mds0 + t), &g_edge[(size_t)tile0 * ETILE + t]);
    CPA_COMMIT();
    CPA_WAIT0();
    __syncthreads();
    sort_tile96(mds0, sinv0, fwd0, srl0, ssc0, segs0, scnt, sbase, swx, t, lane, wrp);
    stage_x(x, mds0, sinv0, xs0, t);
    CPA_COMMIT();
    if (tile0 + grid < ntiles && t < ETILE)
        cpa16(smaddr(mds0 + ETILE + t), &g_edge[(size_t)(tile0 + grid) * ETILE + t]);
    CPA_COMMIT();

    int par = 0, rot = 0;
    for (int tile = tile0; tile < ntiles; tile += grid) {
        CPA_WAIT0();                  // x(tile) staged; meta(tile+g) arrived
        __syncthreads();
        int nseg_cur = swx[6];        // nseg of current tile (set by its sort)
        int nxt = tile + grid;

        float* xs_c  = par ? xs1 : xs0;
        float* xs_n  = par ? xs0 : xs1;
        int*   sinv_n = par ? sinv0 : sinv1;
        int*   fwd_c = par ? fwd1 : fwd0;
        int*   fwd_n = par ? fwd0 : fwd1;
        int*   srl_c = par ? srl1 : srl0;
        int*   srl_n = par ? srl0 : srl1;
        float* ssc_c = par ? ssc1 : ssc0;
        float* ssc_n = par ? ssc0 : ssc1;
        int*   segs_c = par ? segs1 : segs0;
        int*   segs_n = par ? segs0 : segs1;
        const int4* mdc = mds0 + rot * ETILE;

        // ---- sort + stage tile (nxt); prefetch meta(nxt+g) ----
        if (nxt < ntiles) {
            const int4* mdn = mds0 + ((rot + 1) % 3) * ETILE;
            sort_tile96(mdn, sinv_n, fwd_n, srl_n, ssc_n, segs_n,
                        scnt, sbase, swx, t, lane, wrp);
            stage_x(x, mdn, sinv_n, xs_n, t);
        }
        CPA_COMMIT();
        if (nxt + grid < ntiles && t < ETILE)
            cpa16(smaddr(mds0 + ((rot + 2) % 3) * ETILE + t),
                  &g_edge[(size_t)(nxt + grid) * ETILE + t]);
        CPA_COMMIT();

        // ---- phase 2: transform sorted row e (block b), write in place ----
        {
            int rel  = srl_c[e];
            float sc = ssc_c[e];
            float* xp = xs_c + e * 100 + b * CB;
            float xv[CB];
            const float4* xp4 = reinterpret_cast<const float4*>(xp);
#pragma unroll
            for (int k = 0; k < 5; k++) {
                float4 v = xp4[k];
                if (do_relu) {
                    v.x = fmaxf(v.x, 0.0f); v.y = fmaxf(v.y, 0.0f);
                    v.z = fmaxf(v.z, 0.0f); v.w = fmaxf(v.w, 0.0f);
                }
                xv[4 * k + 0] = v.x; xv[4 * k + 1] = v.y;
                xv[4 * k + 2] = v.z; xv[4 * k + 3] = v.w;
            }
            const float* wb = ws + rel * WSTRIDE + b * (CB * CB);
            float acc[CB];
#pragma unroll
            for (int d = 0; d < CB; d++) acc[d] = 0.0f;
#pragma unroll
            for (int c = 0; c < CB; c++) {
                float xvc = xv[c];
                const float4* w4 = reinterpret_cast<const float4*>(wb + c * CB);
#pragma unroll
                for (int d4 = 0; d4 < 5; d4++) {
                    float4 wv = w4[d4];
                    acc[4 * d4 + 0] = fmaf(xvc, wv.x, acc[4 * d4 + 0]);
                    acc[4 * d4 + 1] = fmaf(xvc, wv.y, acc[4 * d4 + 1]);
                    acc[4 * d4 + 2] = fmaf(xvc, wv.z, acc[4 * d4 + 2]);
                    acc[4 * d4 + 3] = fmaf(xvc, wv.w, acc[4 * d4 + 3]);
                }
            }
            float4* wp = reinterpret_cast<float4*>(xp);
#pragma unroll
            for (int d4 = 0; d4 < 5; d4++) {
                float4 v;
                v.x = acc[4 * d4 + 0] * sc; v.y = acc[4 * d4 + 1] * sc;
                v.z = acc[4 * d4 + 2] * sc; v.w = acc[4 * d4 + 3] * sc;
                wp[d4] = v;
            }
        }
        __syncthreads();              // res (in xs_c) complete

        // ---- phase 3: per-dst-segment sum + atomics ----
        for (int s = wrp; s < nseg_cur; s += ETHREADS / 32) {
            int a0 = segs_c[s], a1 = segs_c[s + 1];
            if (lane < 25) {
                float4 a4 = make_float4(0.0f, 0.0f, 0.0f, 0.0f);
                for (int ee = a0; ee < a1; ee++) {
                    int rr = fwd_c[ee];
                    float4 v = *reinterpret_cast<const float4*>(
                        xs_c + rr * 100 + 4 * lane);
                    a4.x += v.x; a4.y += v.y; a4.z += v.z; a4.w += v.w;
                }
                float* op = out + (size_t)mdc[a0].y * HID + 4 * lane;
                atomicAdd(op + 0, a4.x);
                atomicAdd(op + 1, a4.y);
                atomicAdd(op + 2, a4.z);
                atomicAdd(op + 3, a4.w);
            }
        }
        __syncthreads();              // mdc/xs_c readers done before reuse
        rot = (rot + 1) % 3;
        par ^= 1;
    }
}

// ---------------- host launcher ----------------
extern "C" void kernel_launch(void* const* d_in, const int* in_sizes, int n_in,
                              void* d_out, int out_size) {
    const float* node_emb = (const float*)d_in[0];
    const float* w1    = (const float*)d_in[1];
    const float* root1 = (const float*)d_in[2];
    const float* bias1 = (const float*)d_in[3];
    const float* w2    = (const float*)d_in[4];
    const float* root2 = (const float*)d_in[5];
    const float* bias2 = (const float*)d_in[6];
    const int*   eidx  = (const int*)d_in[7];
    const int*   etyp  = (const int*)d_in[8];
    float* out = (float*)d_out;

    int N = in_sizes[0] / HID;
    int E = in_sizes[8];
    if (N > MAXN) N = MAXN;
    int ntiles = (E + ETILE - 1) / ETILE;
    int Epad = ntiles * ETILE;
    if (Epad > MAXE) { Epad = MAXE; ntiles = Epad / ETILE; }

    float* h1 = nullptr;
    cudaGetSymbolAddress((void**)&h1, g_h1);

    const int EDGE_SMEM = (NREL * WSTRIDE + 2 * ETILE * 100) * 4   // ws + xs0/xs1
                        + 3 * ETILE * 16                            // meta x3
                        + (6 * ETILE + 2 * ETILE                    // sinv/fwd/srl x2 + ssc x2
                           + 2 * (ETILE + 1) + 48 + 48 + 8) * 4;
    const int INIT_SMEM = (GROWS * 101 + HID * HID) * 4;
    cudaFuncSetAttribute(k_edge, cudaFuncAttributeMaxDynamicSharedMemorySize, EDGE_SMEM);
    cudaFuncSetAttribute(k_init, cudaFuncAttributeMaxDynamicSharedMemorySize, INIT_SMEM);

    int RN = NREL * N;
    int nb = (N + 1023) / 1024;      // 98 blocks, all resident
    int init_grid = (N + GROWS - 1) / GROWS;
    const int EDGE_GRID = 148;

    // --- preprocessing (recomputed every call; graph-capturable) ---
    k_zero<<<(RN + 255) / 256, 256>>>(N, RN, E, Epad);
    k_count<<<(E + 255) / 256, 256>>>(eidx, etyp, E, N);
    k_scan<<<nb, 1024>>>(N);
    k_scatter<<<(E + 255) / 256, 256>>>(eidx, etyp, E, N);

    // --- layer 1: h1 = node_emb @ root1 + bias1 + block_agg(node_emb) ---
    k_init<<<init_grid, GTHREADS, INIT_SMEM>>>(node_emb, root1, bias1, h1, N, 0);
    k_edge<<<EDGE_GRID, ETHREADS, EDGE_SMEM>>>(node_emb, w1, h1, ntiles, 0);

    // --- layer 2: out = relu(h1) @ root2 + bias2 + block_agg(relu(h1)) ---
    k_init<<<init_grid, GTHREADS, INIT_SMEM>>>(h1, root2, bias2, out, N, 1);
    k_edge<<<EDGE_GRID, ETHREADS, EDGE_SMEM>>>(h1, w2, out, ntiles, 1);
}